// round 6
// baseline (speedup 1.0000x reference)
#include <cuda_runtime.h>
#include <cuda_bf16.h>
#include <math.h>

#define BATCH   8
#define TT      2048
#define BT      16384      // BATCH*TT
#define DMODEL  1024
#define NP      512        // padded projection columns (450 real)
#define RECW    516        // floats per (b,t) record (float4 aligned)
#define K1EXP   3072       // 3 * 1024  (bf16 split blocks: [hi, lo, hi])
#define K2EXP   384        // 12 * 32   (interleaved per-lane triplets)

// ---------------- device scratch (no allocations allowed) ----------------
__device__ __align__(16) __nv_bfloat16 g_Uexp[(size_t)BT * K1EXP];      // A for GEMM1
__device__ __align__(16) __nv_bfloat16 g_B1[(size_t)NP * K1EXP];        // B for GEMM1
__device__ __align__(16) __nv_bfloat16 g_B2[(size_t)DMODEL * K2EXP];    // B for GEMM2
__device__ __align__(16) __nv_bfloat16 g_Hexp[(size_t)BT * K2EXP];      // A for GEMM2
__device__ __align__(16) float g_Hraw[(size_t)BT * 128];                // raw scan output fp32
__device__ float g_P[(size_t)BT * NP];                                  // raw projections fp32
__device__ __align__(16) float g_rec[(size_t)BT * RECW];                // derived scan records

// ---------------- helpers ----------------
__device__ __forceinline__ void split_bf16(float v, __nv_bfloat16& hi, __nv_bfloat16& lo)
{
    hi = __float2bfloat16(v);
    lo = __float2bfloat16(v - __bfloat162float(hi));
}

__device__ __forceinline__ unsigned pack2(__nv_bfloat16 a, __nv_bfloat16 b)
{
    __nv_bfloat162 p(a, b);
    return *(unsigned*)&p;
}

// ---------------- U -> bf16 hi/lo expansion: Uexp[bt][3K] = [hi | lo | hi] ----------------
__global__ void conv_u(const float* __restrict__ u)
{
    size_t i = (size_t)blockIdx.x * 256 + threadIdx.x;
    size_t row = i >> 8;
    int c = (int)(i & 255) * 4;
    float4 v = *(const float4*)(u + row * DMODEL + c);
    __nv_bfloat16 h[4], l[4];
    split_bf16(v.x, h[0], l[0]); split_bf16(v.y, h[1], l[1]);
    split_bf16(v.z, h[2], l[2]); split_bf16(v.w, h[3], l[3]);
    __nv_bfloat16* base = g_Uexp + row * K1EXP;
    *(uint2*)(base + c)        = *(uint2*)h;
    *(uint2*)(base + 1024 + c) = *(uint2*)l;
    *(uint2*)(base + 2048 + c) = *(uint2*)h;
}

// ---------------- pack B1[n][3K]: blocks [Bh | Bh | Bl] ----------------
__global__ void pack_b1(const float* __restrict__ W_A, const float* __restrict__ W_k,
                        const float* __restrict__ W_beta, const float* __restrict__ B_w)
{
    int idx = blockIdx.x * 256 + threadIdx.x;
    if (idx >= NP * DMODEL) return;
    int n = idx >> 10, k = idx & 1023;
    float v = 0.f;
    if (n < 64)        v = W_A[n * DMODEL + k];
    else if (n < 320)  v = W_k[(size_t)(n - 64) * DMODEL + k];
    else if (n < 322)  v = W_beta[(n - 320) * DMODEL + k];
    else if (n < 450)  v = B_w[(size_t)(n - 322) * DMODEL + k];
    __nv_bfloat16 hi, lo; split_bf16(v, hi, lo);
    __nv_bfloat16* base = g_B1 + (size_t)n * K1EXP;
    base[k] = hi; base[1024 + k] = hi; base[2048 + k] = lo;
}

// ---------------- pack B2[d][384]: k = 12*l + 3*i + s ; (Ch,Ch,Cl), n=l+32i ------
__global__ void pack_b2(const float* __restrict__ C)
{
    int idx = blockIdx.x * 256 + threadIdx.x;
    if (idx >= DMODEL * 128) return;
    int d = idx >> 7, n = idx & 127;
    int l = n & 31, i = n >> 5;
    float v = C[(size_t)d * 128 + n];
    __nv_bfloat16 hi, lo; split_bf16(v, hi, lo);
    __nv_bfloat16* base = g_B2 + (size_t)d * K2EXP + 12 * l + 3 * i;
    base[0] = hi; base[1] = hi; base[2] = lo;
}

// ---------------- bf16 HMMA GEMM (proven, unchanged) ----------
template <int KTOT, int LDA, int LDB>
__global__ __launch_bounds__(256)
void mma_gemm(const __nv_bfloat16* __restrict__ A, const __nv_bfloat16* __restrict__ B,
              float* __restrict__ Cout, int ldc,
              const float* __restrict__ uPtr, const float* __restrict__ Dvec)
{
    __shared__ unsigned sA[2][128 * 16];
    __shared__ unsigned sB[2][128 * 16];

    const int tid  = threadIdx.x;
    const int m0   = blockIdx.y * 128;
    const int n0   = blockIdx.x * 128;
    const int lrow = tid >> 1, half = tid & 1;
    const int wid  = tid >> 5, lane = tid & 31;
    const int wm   = wid >> 1, wn = wid & 1;
    const int grp  = lane >> 2, tig = lane & 3;

    const uint4* Ag = (const uint4*)A + (size_t)(m0 + lrow) * (LDA / 8) + half * 2;
    const uint4* Bg = (const uint4*)B + (size_t)(n0 + lrow) * (LDB / 8) + half * 2;

    const int sw    = (lrow & 7) << 1;
    const int sbase = lrow * 16;
    const int w0    = half * 8;

    float acc[2][8][4];
#pragma unroll
    for (int im = 0; im < 2; im++)
#pragma unroll
        for (int in = 0; in < 8; in++)
#pragma unroll
            for (int q = 0; q < 4; q++) acc[im][in][q] = 0.f;

    constexpr int KIT = KTOT / 32;

    uint4 pa0 = Ag[0], pa1 = Ag[1], pb0 = Bg[0], pb1 = Bg[1];
    Ag += 4; Bg += 4;

#define STILE(dst, v0, v1)                                                              \
    do {                                                                                \
        ((uint2*)(dst))[(sbase + ((w0 + 0) ^ sw)) >> 1] = make_uint2((v0).x, (v0).y);   \
        ((uint2*)(dst))[(sbase + ((w0 + 2) ^ sw)) >> 1] = make_uint2((v0).z, (v0).w);   \
        ((uint2*)(dst))[(sbase + ((w0 + 4) ^ sw)) >> 1] = make_uint2((v1).x, (v1).y);   \
        ((uint2*)(dst))[(sbase + ((w0 + 6) ^ sw)) >> 1] = make_uint2((v1).z, (v1).w);   \
    } while (0)

    STILE(sA[0], pa0, pa1);
    STILE(sB[0], pb0, pb1);
    __syncthreads();

    for (int it = 0; it < KIT; it++) {
        const int cur = it & 1, nxt = cur ^ 1;
        if (it + 1 < KIT) {
            pa0 = Ag[0]; pa1 = Ag[1]; pb0 = Bg[0]; pb1 = Bg[1];
            Ag += 4; Bg += 4;
        }
        const unsigned* cA = sA[cur];
        const unsigned* cB = sB[cur];

#pragma unroll
        for (int kk = 0; kk < 2; kk++) {
            unsigned af[2][4], bf[8][2];
#pragma unroll
            for (int im = 0; im < 2; im++) {
                int r0 = wm * 32 + im * 16 + grp;
                int r1 = r0 + 8;
                int s0 = (r0 & 7) << 1;
                int s1 = (r1 & 7) << 1;
                af[im][0] = cA[r0 * 16 + ((kk * 8 + tig) ^ s0)];
                af[im][1] = cA[r1 * 16 + ((kk * 8 + tig) ^ s1)];
                af[im][2] = cA[r0 * 16 + ((kk * 8 + 4 + tig) ^ s0)];
                af[im][3] = cA[r1 * 16 + ((kk * 8 + 4 + tig) ^ s1)];
            }
#pragma unroll
            for (int in = 0; in < 8; in++) {
                int nr = wn * 64 + in * 8 + grp;
                int s  = (nr & 7) << 1;
                bf[in][0] = cB[nr * 16 + ((kk * 8 + tig) ^ s)];
                bf[in][1] = cB[nr * 16 + ((kk * 8 + 4 + tig) ^ s)];
            }
#pragma unroll
            for (int im = 0; im < 2; im++)
#pragma unroll
                for (int in = 0; in < 8; in++) {
                    float* c = acc[im][in];
                    asm volatile(
                        "mma.sync.aligned.m16n8k16.row.col.f32.bf16.bf16.f32 "
                        "{%0,%1,%2,%3}, {%4,%5,%6,%7}, {%8,%9}, {%0,%1,%2,%3};\n"
                        : "+f"(c[0]), "+f"(c[1]), "+f"(c[2]), "+f"(c[3])
                        : "r"(af[im][0]), "r"(af[im][1]), "r"(af[im][2]), "r"(af[im][3]),
                          "r"(bf[in][0]), "r"(bf[in][1]));
                }
        }

        if (it + 1 < KIT) {
            STILE(sA[nxt], pa0, pa1);
            STILE(sB[nxt], pb0, pb1);
            __syncthreads();
        }
    }
#undef STILE

#pragma unroll
    for (int im = 0; im < 2; im++) {
#pragma unroll
        for (int in = 0; in < 8; in++) {
            int row = m0 + wm * 32 + im * 16 + grp;
            int col = n0 + wn * 64 + in * 8 + tig * 2;
            float2 v01 = make_float2(acc[im][in][0], acc[im][in][1]);
            float2 v23 = make_float2(acc[im][in][2], acc[im][in][3]);
            if (uPtr) {
                size_t b0 = (size_t)row * ldc + col;
                size_t b1 = (size_t)(row + 8) * ldc + col;
                v01.x += uPtr[b0] * Dvec[col];
                v01.y += uPtr[b0 + 1] * Dvec[col + 1];
                v23.x += uPtr[b1] * Dvec[col];
                v23.y += uPtr[b1 + 1] * Dvec[col + 1];
            }
            *(float2*)(Cout + (size_t)row * ldc + col)       = v01;
            *(float2*)(Cout + (size_t)(row + 8) * ldc + col) = v23;
        }
    }
}

// ---------------- derive: projections -> per-step record (R4 float4-lane layout) ----------
// record floats: [0,128) rot: lane l -> (S0,S1,D0,D1) at 4l ; [128,256) k1 (4l+i = n l+32i)
// [256,384) k2 ; [384,512) B ; [512] be1 [513] be2 [514] cc [515] pad
__global__ void derive_kernel(const float* __restrict__ bA, const float* __restrict__ bk,
                              const float* __restrict__ bbeta, const float* __restrict__ Bb)
{
    const int bt = blockIdx.x;
    const int n = threadIdx.x;               // 0..127
    const int l = n & 31, i = n >> 5;
    const float* p = g_P + (size_t)bt * NP;
    float* rc = g_rec + (size_t)bt * RECW;

    if (n < 64) {
        float a = fminf(fmaxf(p[n] + bA[n], 0.f), 100.f);
        float S = 1.f / (1.f + 0.01f * a);
        rc[4 * l + i]     = S;
        rc[4 * l + 2 + i] = 0.1f * a * S;    // DT*A*S
    }
    float k1 = p[64 + n]  + bk[n];
    float k2 = p[192 + n] + bk[128 + n];
    float Bv = p[322 + n] + Bb[n];

    float s1 = k1 * k1, s2 = k2 * k2, sx = k1 * k2;
#pragma unroll
    for (int off = 16; off; off >>= 1) {
        s1 += __shfl_xor_sync(0xffffffffu, s1, off);
        s2 += __shfl_xor_sync(0xffffffffu, s2, off);
        sx += __shfl_xor_sync(0xffffffffu, sx, off);
    }
    __shared__ float sm[12];
    __shared__ float bc[2];
    int w = n >> 5;
    if ((n & 31) == 0) { sm[w] = s1; sm[4 + w] = s2; sm[8 + w] = sx; }
    __syncthreads();
    if (n == 0) {
        float q1 = sm[0] + sm[1] + sm[2] + sm[3];
        float q2 = sm[4] + sm[5] + sm[6] + sm[7];
        float qx = sm[8] + sm[9] + sm[10] + sm[11];
        float i1 = 1.f / fmaxf(sqrtf(q1), 1e-12f);
        float i2 = 1.f / fmaxf(sqrtf(q2), 1e-12f);
        float be1 = 2.f / (1.f + expf(-(p[320] + bbeta[0])));
        float be2 = 2.f / (1.f + expf(-(p[321] + bbeta[1])));
        rc[512] = be1;
        rc[513] = be2;
        rc[514] = be1 * qx * i1 * i2;        // cc
        bc[0] = i1; bc[1] = i2;
    }
    __syncthreads();
    rc[128 + 4 * l + i] = k1 * bc[0];
    rc[256 + 4 * l + i] = k2 * bc[1];
    rc[384 + 4 * l + i] = Bv;
}

// ---------------- scan: TWO independent batches per warp (latency hiding), fp32 out -------
__global__ __launch_bounds__(32)
void scan_kernel()
{
    const int lane = threadIdx.x;
    const size_t bA = (size_t)blockIdx.x * 2;
    const float4* __restrict__ rA = (const float4*)g_rec + bA * TT * (RECW / 4);
    const float4* __restrict__ rB = rA + (size_t)TT * (RECW / 4);
    float* __restrict__ oA = g_Hraw + bA * TT * 128;
    float* __restrict__ oB = oA + (size_t)TT * 128;

    float A0 = 0.f, A1 = 0.f, A2 = 0.f, A3 = 0.f;   // state batch A
    float B0 = 0.f, B1 = 0.f, B2 = 0.f, B3 = 0.f;   // state batch B

    float4 Asv[2], Aav[2], Acv[2], Abv[2], Aev[2];
    float4 Bsv[2], Bav[2], Bcv[2], Bbv[2], Bev[2];
#pragma unroll
    for (int p = 0; p < 2; p++) {
        const float4* ra = rA + (size_t)p * (RECW / 4);
        const float4* rb = rB + (size_t)p * (RECW / 4);
        Asv[p] = ra[lane]; Aav[p] = ra[32 + lane]; Acv[p] = ra[64 + lane];
        Abv[p] = ra[96 + lane]; Aev[p] = ra[128];
        Bsv[p] = rb[lane]; Bav[p] = rb[32 + lane]; Bcv[p] = rb[64 + lane];
        Bbv[p] = rb[96 + lane]; Bev[p] = rb[128];
    }

#pragma unroll 2
    for (int t = 0; t < TT; t++) {
        const int s = t & 1;
        const float4 aS = Asv[s], aK1 = Aav[s], aK2 = Acv[s], aB = Abv[s], aE = Aev[s];
        const float4 bS = Bsv[s], bK1 = Bav[s], bK2 = Bcv[s], bB = Bbv[s], bE = Bev[s];

        if (t + 2 < TT) {
            const float4* ra = rA + (size_t)(t + 2) * (RECW / 4);
            const float4* rb = rB + (size_t)(t + 2) * (RECW / 4);
            Asv[s] = ra[lane]; Aav[s] = ra[32 + lane]; Acv[s] = ra[64 + lane];
            Abv[s] = ra[96 + lane]; Aev[s] = ra[128];
            Bsv[s] = rb[lane]; Bav[s] = rb[32 + lane]; Bcv[s] = rb[64 + lane];
            Bbv[s] = rb[96 + lane]; Bev[s] = rb[128];
        }

        // --- rotations (independent chains) ---
        float az0 = fmaf(-aS.z, A2, aS.x * A0);
        float az1 = fmaf(-aS.w, A3, aS.y * A1);
        float ay2 = aS.x * fmaf(0.1f, A0, A2);
        float ay3 = aS.y * fmaf(0.1f, A1, A3);
        float bz0 = fmaf(-bS.z, B2, bS.x * B0);
        float bz1 = fmaf(-bS.w, B3, bS.y * B1);
        float by2 = bS.x * fmaf(0.1f, B0, B2);
        float by3 = bS.y * fmaf(0.1f, B1, B3);

        // --- dot partials ---
        float ad1 = fmaf(aK1.x, az0, aK1.y * az1); ad1 = fmaf(aK1.z, ay2, ad1); ad1 = fmaf(aK1.w, ay3, ad1);
        float ad2 = fmaf(aK2.x, az0, aK2.y * az1); ad2 = fmaf(aK2.z, ay2, ad2); ad2 = fmaf(aK2.w, ay3, ad2);
        float bd1 = fmaf(bK1.x, bz0, bK1.y * bz1); bd1 = fmaf(bK1.z, by2, bd1); bd1 = fmaf(bK1.w, by3, bd1);
        float bd2 = fmaf(bK2.x, bz0, bK2.y * bz1); bd2 = fmaf(bK2.z, by2, bd2); bd2 = fmaf(bK2.w, by3, bd2);

        // --- four interleaved butterflies ---
#pragma unroll
        for (int off = 16; off; off >>= 1) {
            ad1 += __shfl_xor_sync(0xffffffffu, ad1, off);
            ad2 += __shfl_xor_sync(0xffffffffu, ad2, off);
            bd1 += __shfl_xor_sync(0xffffffffu, bd1, off);
            bd2 += __shfl_xor_sync(0xffffffffu, bd2, off);
        }

        float aa1 = aE.x * ad1;
        float aa2 = aE.y * fmaf(-aE.z, ad1, ad2);
        float ba1 = bE.x * bd1;
        float ba2 = bE.y * fmaf(-bE.z, bd1, bd2);

        A0 = fmaf(-aa2, aK2.x, fmaf(-aa1, aK1.x, az0 + aB.x));
        A1 = fmaf(-aa2, aK2.y, fmaf(-aa1, aK1.y, az1 + aB.y));
        A2 = fmaf(-aa2, aK2.z, fmaf(-aa1, aK1.z, ay2 + aB.z));
        A3 = fmaf(-aa2, aK2.w, fmaf(-aa1, aK1.w, ay3 + aB.w));
        B0 = fmaf(-ba2, bK2.x, fmaf(-ba1, bK1.x, bz0 + bB.x));
        B1 = fmaf(-ba2, bK2.y, fmaf(-ba1, bK1.y, bz1 + bB.y));
        B2 = fmaf(-ba2, bK2.z, fmaf(-ba1, bK1.z, by2 + bB.z));
        B3 = fmaf(-ba2, bK2.w, fmaf(-ba1, bK1.w, by3 + bB.w));

        *((float4*)(oA + (size_t)t * 128) + lane) = make_float4(A0, A1, A2, A3);
        *((float4*)(oB + (size_t)t * 128) + lane) = make_float4(B0, B1, B2, B3);
    }
}

// ---------------- conv_h: raw fp32 h -> bf16 hi/lo triplets for GEMM2 ----------------
__global__ void conv_h()
{
    int idx = blockIdx.x * 256 + threadIdx.x;   // BT*32
    int bt = idx >> 5;
    int l = idx & 31;
    float4 hv = *((const float4*)g_Hraw + (size_t)bt * 32 + l);
    __nv_bfloat16 h[4], lo[4];
    split_bf16(hv.x, h[0], lo[0]); split_bf16(hv.y, h[1], lo[1]);
    split_bf16(hv.z, h[2], lo[2]); split_bf16(hv.w, h[3], lo[3]);
    unsigned w0 = pack2(h[0], lo[0]);
    unsigned w1 = pack2(h[0], h[1]);
    unsigned w2 = pack2(lo[1], h[1]);
    unsigned w3 = pack2(h[2], lo[2]);
    unsigned w4 = pack2(h[2], h[3]);
    unsigned w5 = pack2(lo[3], h[3]);
    uint2* op = (uint2*)(g_Hexp + (size_t)bt * K2EXP) + 3 * l;
    op[0] = make_uint2(w0, w1);
    op[1] = make_uint2(w2, w3);
    op[2] = make_uint2(w4, w5);
}

// ---------------- launch ----------------
extern "C" void kernel_launch(void* const* d_in, const int* in_sizes, int n_in,
                              void* d_out, int out_size)
{
    const float* u      = (const float*)d_in[0];
    const float* W_A    = (const float*)d_in[1];
    const float* b_A    = (const float*)d_in[2];
    const float* W_k    = (const float*)d_in[3];
    const float* b_k    = (const float*)d_in[4];
    const float* W_beta = (const float*)d_in[5];
    const float* b_beta = (const float*)d_in[6];
    const float* B_w    = (const float*)d_in[7];
    const float* B_b    = (const float*)d_in[8];
    const float* C      = (const float*)d_in[9];
    const float* D      = (const float*)d_in[10];
    float* out = (float*)d_out;

    pack_b1<<<(NP * DMODEL + 255) / 256, 256>>>(W_A, W_k, W_beta, B_w);
    pack_b2<<<(DMODEL * 128 + 255) / 256, 256>>>(C);
    conv_u<<<(BT * (DMODEL / 4)) / 256, 256>>>(u);

    // GEMM1: P[16384 x 512] = Uexp[16384 x 3072] * B1^T
    {
        __nv_bfloat16 *dA, *dB; float* dP;
        cudaGetSymbolAddress((void**)&dA, g_Uexp);
        cudaGetSymbolAddress((void**)&dB, g_B1);
        cudaGetSymbolAddress((void**)&dP, g_P);
        mma_gemm<K1EXP, K1EXP, K1EXP><<<dim3(NP / 128, BT / 128), 256>>>(
            dA, dB, dP, NP, nullptr, nullptr);
    }

    derive_kernel<<<BT, 128>>>(b_A, b_k, b_beta, B_b);

    scan_kernel<<<BATCH / 2, 32>>>();
    conv_h<<<(BT * 32) / 256, 256>>>();

    // GEMM2: out[16384 x 1024] = Hexp[16384 x 384] * B2^T + u * D
    {
        __nv_bfloat16 *dA, *dB;
        cudaGetSymbolAddress((void**)&dA, g_Hexp);
        cudaGetSymbolAddress((void**)&dB, g_B2);
        mma_gemm<K2EXP, K2EXP, K2EXP><<<dim3(DMODEL / 128, BT / 128), 256>>>(
            dA, dB, out, DMODEL, u, D);
    }
}

// round 7
// speedup vs baseline: 1.1346x; 1.1346x over previous
#include <cuda_runtime.h>
#include <cuda_bf16.h>
#include <math.h>

#define BATCH   8
#define TT      2048
#define BT      16384      // BATCH*TT
#define DMODEL  1024
#define NP      512        // padded projection columns (450 real)
#define RECW    516        // floats per (b,t) record (float4 aligned)
#define K1EXP   3072       // 3 * 1024  (bf16 split blocks: [hi, lo, hi])
#define K2EXP   384        // 12 * 32   (interleaved per-lane triplets)

// ---------------- device scratch (no allocations allowed) ----------------
__device__ __align__(16) __nv_bfloat16 g_Uexp[(size_t)BT * K1EXP];      // A for GEMM1
__device__ __align__(16) __nv_bfloat16 g_B1[(size_t)NP * K1EXP];        // B for GEMM1
__device__ __align__(16) __nv_bfloat16 g_B2[(size_t)DMODEL * K2EXP];    // B for GEMM2
__device__ __align__(16) __nv_bfloat16 g_Hexp[(size_t)BT * K2EXP];      // A for GEMM2
__device__ __align__(16) float g_Hraw[(size_t)BT * 128];                // raw scan output fp32
__device__ float g_P[(size_t)BT * NP];                                  // raw projections fp32
__device__ __align__(16) float g_rec[(size_t)BT * RECW];                // derived scan records

// ---------------- helpers ----------------
__device__ __forceinline__ void split_bf16(float v, __nv_bfloat16& hi, __nv_bfloat16& lo)
{
    hi = __float2bfloat16(v);
    lo = __float2bfloat16(v - __bfloat162float(hi));
}

__device__ __forceinline__ unsigned pack2(__nv_bfloat16 a, __nv_bfloat16 b)
{
    __nv_bfloat162 p(a, b);
    return *(unsigned*)&p;
}

// ---------------- U -> bf16 hi/lo expansion: Uexp[bt][3K] = [hi | lo | hi] ----------------
__global__ void conv_u(const float* __restrict__ u)
{
    size_t i = (size_t)blockIdx.x * 256 + threadIdx.x;
    size_t row = i >> 8;
    int c = (int)(i & 255) * 4;
    float4 v = *(const float4*)(u + row * DMODEL + c);
    __nv_bfloat16 h[4], l[4];
    split_bf16(v.x, h[0], l[0]); split_bf16(v.y, h[1], l[1]);
    split_bf16(v.z, h[2], l[2]); split_bf16(v.w, h[3], l[3]);
    __nv_bfloat16* base = g_Uexp + row * K1EXP;
    *(uint2*)(base + c)        = *(uint2*)h;
    *(uint2*)(base + 1024 + c) = *(uint2*)l;
    *(uint2*)(base + 2048 + c) = *(uint2*)h;
}

// ---------------- pack B1[n][3K]: blocks [Bh | Bh | Bl] ----------------
__global__ void pack_b1(const float* __restrict__ W_A, const float* __restrict__ W_k,
                        const float* __restrict__ W_beta, const float* __restrict__ B_w)
{
    int idx = blockIdx.x * 256 + threadIdx.x;
    if (idx >= NP * DMODEL) return;
    int n = idx >> 10, k = idx & 1023;
    float v = 0.f;
    if (n < 64)        v = W_A[n * DMODEL + k];
    else if (n < 320)  v = W_k[(size_t)(n - 64) * DMODEL + k];
    else if (n < 322)  v = W_beta[(n - 320) * DMODEL + k];
    else if (n < 450)  v = B_w[(size_t)(n - 322) * DMODEL + k];
    __nv_bfloat16 hi, lo; split_bf16(v, hi, lo);
    __nv_bfloat16* base = g_B1 + (size_t)n * K1EXP;
    base[k] = hi; base[1024 + k] = hi; base[2048 + k] = lo;
}

// ---------------- pack B2[d][384]: k = 12*l + 3*i + s ; (Ch,Ch,Cl), n=l+32i ------
__global__ void pack_b2(const float* __restrict__ C)
{
    int idx = blockIdx.x * 256 + threadIdx.x;
    if (idx >= DMODEL * 128) return;
    int d = idx >> 7, n = idx & 127;
    int l = n & 31, i = n >> 5;
    float v = C[(size_t)d * 128 + n];
    __nv_bfloat16 hi, lo; split_bf16(v, hi, lo);
    __nv_bfloat16* base = g_B2 + (size_t)d * K2EXP + 12 * l + 3 * i;
    base[0] = hi; base[1] = hi; base[2] = lo;
}

// ---------------- bf16 HMMA GEMM (proven, unchanged) ----------
template <int KTOT, int LDA, int LDB>
__global__ __launch_bounds__(256)
void mma_gemm(const __nv_bfloat16* __restrict__ A, const __nv_bfloat16* __restrict__ B,
              float* __restrict__ Cout, int ldc,
              const float* __restrict__ uPtr, const float* __restrict__ Dvec)
{
    __shared__ unsigned sA[2][128 * 16];
    __shared__ unsigned sB[2][128 * 16];

    const int tid  = threadIdx.x;
    const int m0   = blockIdx.y * 128;
    const int n0   = blockIdx.x * 128;
    const int lrow = tid >> 1, half = tid & 1;
    const int wid  = tid >> 5, lane = tid & 31;
    const int wm   = wid >> 1, wn = wid & 1;
    const int grp  = lane >> 2, tig = lane & 3;

    const uint4* Ag = (const uint4*)A + (size_t)(m0 + lrow) * (LDA / 8) + half * 2;
    const uint4* Bg = (const uint4*)B + (size_t)(n0 + lrow) * (LDB / 8) + half * 2;

    const int sw    = (lrow & 7) << 1;
    const int sbase = lrow * 16;
    const int w0    = half * 8;

    float acc[2][8][4];
#pragma unroll
    for (int im = 0; im < 2; im++)
#pragma unroll
        for (int in = 0; in < 8; in++)
#pragma unroll
            for (int q = 0; q < 4; q++) acc[im][in][q] = 0.f;

    constexpr int KIT = KTOT / 32;

    uint4 pa0 = Ag[0], pa1 = Ag[1], pb0 = Bg[0], pb1 = Bg[1];
    Ag += 4; Bg += 4;

#define STILE(dst, v0, v1)                                                              \
    do {                                                                                \
        ((uint2*)(dst))[(sbase + ((w0 + 0) ^ sw)) >> 1] = make_uint2((v0).x, (v0).y);   \
        ((uint2*)(dst))[(sbase + ((w0 + 2) ^ sw)) >> 1] = make_uint2((v0).z, (v0).w);   \
        ((uint2*)(dst))[(sbase + ((w0 + 4) ^ sw)) >> 1] = make_uint2((v1).x, (v1).y);   \
        ((uint2*)(dst))[(sbase + ((w0 + 6) ^ sw)) >> 1] = make_uint2((v1).z, (v1).w);   \
    } while (0)

    STILE(sA[0], pa0, pa1);
    STILE(sB[0], pb0, pb1);
    __syncthreads();

    for (int it = 0; it < KIT; it++) {
        const int cur = it & 1, nxt = cur ^ 1;
        if (it + 1 < KIT) {
            pa0 = Ag[0]; pa1 = Ag[1]; pb0 = Bg[0]; pb1 = Bg[1];
            Ag += 4; Bg += 4;
        }
        const unsigned* cA = sA[cur];
        const unsigned* cB = sB[cur];

#pragma unroll
        for (int kk = 0; kk < 2; kk++) {
            unsigned af[2][4], bf[8][2];
#pragma unroll
            for (int im = 0; im < 2; im++) {
                int r0 = wm * 32 + im * 16 + grp;
                int r1 = r0 + 8;
                int s0 = (r0 & 7) << 1;
                int s1 = (r1 & 7) << 1;
                af[im][0] = cA[r0 * 16 + ((kk * 8 + tig) ^ s0)];
                af[im][1] = cA[r1 * 16 + ((kk * 8 + tig) ^ s1)];
                af[im][2] = cA[r0 * 16 + ((kk * 8 + 4 + tig) ^ s0)];
                af[im][3] = cA[r1 * 16 + ((kk * 8 + 4 + tig) ^ s1)];
            }
#pragma unroll
            for (int in = 0; in < 8; in++) {
                int nr = wn * 64 + in * 8 + grp;
                int s  = (nr & 7) << 1;
                bf[in][0] = cB[nr * 16 + ((kk * 8 + tig) ^ s)];
                bf[in][1] = cB[nr * 16 + ((kk * 8 + 4 + tig) ^ s)];
            }
#pragma unroll
            for (int im = 0; im < 2; im++)
#pragma unroll
                for (int in = 0; in < 8; in++) {
                    float* c = acc[im][in];
                    asm volatile(
                        "mma.sync.aligned.m16n8k16.row.col.f32.bf16.bf16.f32 "
                        "{%0,%1,%2,%3}, {%4,%5,%6,%7}, {%8,%9}, {%0,%1,%2,%3};\n"
                        : "+f"(c[0]), "+f"(c[1]), "+f"(c[2]), "+f"(c[3])
                        : "r"(af[im][0]), "r"(af[im][1]), "r"(af[im][2]), "r"(af[im][3]),
                          "r"(bf[in][0]), "r"(bf[in][1]));
                }
        }

        if (it + 1 < KIT) {
            STILE(sA[nxt], pa0, pa1);
            STILE(sB[nxt], pb0, pb1);
            __syncthreads();
        }
    }
#undef STILE

#pragma unroll
    for (int im = 0; im < 2; im++) {
#pragma unroll
        for (int in = 0; in < 8; in++) {
            int row = m0 + wm * 32 + im * 16 + grp;
            int col = n0 + wn * 64 + in * 8 + tig * 2;
            float2 v01 = make_float2(acc[im][in][0], acc[im][in][1]);
            float2 v23 = make_float2(acc[im][in][2], acc[im][in][3]);
            if (uPtr) {
                size_t b0 = (size_t)row * ldc + col;
                size_t b1 = (size_t)(row + 8) * ldc + col;
                v01.x += uPtr[b0] * Dvec[col];
                v01.y += uPtr[b0 + 1] * Dvec[col + 1];
                v23.x += uPtr[b1] * Dvec[col];
                v23.y += uPtr[b1 + 1] * Dvec[col + 1];
            }
            *(float2*)(Cout + (size_t)row * ldc + col)       = v01;
            *(float2*)(Cout + (size_t)(row + 8) * ldc + col) = v23;
        }
    }
}

// ---------------- derive: projections -> per-step record (float4-lane layout) ----------
// record floats: [0,128) rot: lane l -> (S0,S1,D0,D1) at 4l ; [128,256) k1 (4l+i = n l+32i)
// [256,384) k2 ; [384,512) B ; [512] be1 [513] be2 [514] cc [515] pad
__global__ void derive_kernel(const float* __restrict__ bA, const float* __restrict__ bk,
                              const float* __restrict__ bbeta, const float* __restrict__ Bb)
{
    const int bt = blockIdx.x;
    const int n = threadIdx.x;               // 0..127
    const int l = n & 31, i = n >> 5;
    const float* p = g_P + (size_t)bt * NP;
    float* rc = g_rec + (size_t)bt * RECW;

    if (n < 64) {
        float a = fminf(fmaxf(p[n] + bA[n], 0.f), 100.f);
        float S = 1.f / (1.f + 0.01f * a);
        rc[4 * l + i]     = S;
        rc[4 * l + 2 + i] = 0.1f * a * S;    // DT*A*S
    }
    float k1 = p[64 + n]  + bk[n];
    float k2 = p[192 + n] + bk[128 + n];
    float Bv = p[322 + n] + Bb[n];

    float s1 = k1 * k1, s2 = k2 * k2, sx = k1 * k2;
#pragma unroll
    for (int off = 16; off; off >>= 1) {
        s1 += __shfl_xor_sync(0xffffffffu, s1, off);
        s2 += __shfl_xor_sync(0xffffffffu, s2, off);
        sx += __shfl_xor_sync(0xffffffffu, sx, off);
    }
    __shared__ float sm[12];
    __shared__ float bc[2];
    int w = n >> 5;
    if ((n & 31) == 0) { sm[w] = s1; sm[4 + w] = s2; sm[8 + w] = sx; }
    __syncthreads();
    if (n == 0) {
        float q1 = sm[0] + sm[1] + sm[2] + sm[3];
        float q2 = sm[4] + sm[5] + sm[6] + sm[7];
        float qx = sm[8] + sm[9] + sm[10] + sm[11];
        float i1 = 1.f / fmaxf(sqrtf(q1), 1e-12f);
        float i2 = 1.f / fmaxf(sqrtf(q2), 1e-12f);
        float be1 = 2.f / (1.f + expf(-(p[320] + bbeta[0])));
        float be2 = 2.f / (1.f + expf(-(p[321] + bbeta[1])));
        rc[512] = be1;
        rc[513] = be2;
        rc[514] = be1 * qx * i1 * i2;        // cc
        bc[0] = i1; bc[1] = i2;
    }
    __syncthreads();
    rc[128 + 4 * l + i] = k1 * bc[0];
    rc[256 + 4 * l + i] = k2 * bc[1];
    rc[384 + 4 * l + i] = Bv;
}

// ---------------- scan: 1 batch/warp, radix-4 butterfly (independent shuffles), fp32 out ---
__global__ __launch_bounds__(32)
void scan_kernel()
{
    const int b = blockIdx.x, lane = threadIdx.x;
    const float4* __restrict__ r4 = (const float4*)g_rec + (size_t)b * TT * (RECW / 4);
    float* __restrict__ o = g_Hraw + (size_t)b * TT * 128;

    float h0 = 0.f, h1 = 0.f, h2 = 0.f, h3 = 0.f;

    float4 sv[2], av[2], cv[2], bv[2], ev[2];
#pragma unroll
    for (int p = 0; p < 2; p++) {
        const float4* rp = r4 + (size_t)p * (RECW / 4);
        sv[p] = rp[lane];      av[p] = rp[32 + lane];
        cv[p] = rp[64 + lane]; bv[p] = rp[96 + lane];
        ev[p] = rp[128];
    }

#pragma unroll 4
    for (int t = 0; t < TT; t++) {
        const int s = t & 1;
        const float4 S = sv[s], A = av[s], Cv = cv[s], Bv = bv[s], E = ev[s];

        if (t + 2 < TT) {
            const float4* rp = r4 + (size_t)(t + 2) * (RECW / 4);
            sv[s] = rp[lane];      av[s] = rp[32 + lane];
            cv[s] = rp[64 + lane]; bv[s] = rp[96 + lane];
            ev[s] = rp[128];
        }

        // rotation: z_new = S*z - (DT*A*S)*y ; y_new = S*(DT*z + y)
        float z0 = fmaf(-S.z, h2, S.x * h0);
        float z1 = fmaf(-S.w, h3, S.y * h1);
        float y2 = S.x * fmaf(0.1f, h0, h2);
        float y3 = S.y * fmaf(0.1f, h1, h3);

        // dot partials
        float d1 = fmaf(A.x, z0, A.y * z1); d1 = fmaf(A.z, y2, d1); d1 = fmaf(A.w, y3, d1);
        float d2 = fmaf(Cv.x, z0, Cv.y * z1); d2 = fmaf(Cv.z, y2, d2); d2 = fmaf(Cv.w, y3, d2);

        // radix-4 butterfly: all shuffles within a level are independent
        {
            float a1s = __shfl_xor_sync(0xffffffffu, d1, 1);
            float a2s = __shfl_xor_sync(0xffffffffu, d1, 2);
            float a3s = __shfl_xor_sync(0xffffffffu, d1, 3);
            float b1s = __shfl_xor_sync(0xffffffffu, d2, 1);
            float b2s = __shfl_xor_sync(0xffffffffu, d2, 2);
            float b3s = __shfl_xor_sync(0xffffffffu, d2, 3);
            d1 = (d1 + a1s) + (a2s + a3s);
            d2 = (d2 + b1s) + (b2s + b3s);
            a1s = __shfl_xor_sync(0xffffffffu, d1, 4);
            a2s = __shfl_xor_sync(0xffffffffu, d1, 8);
            a3s = __shfl_xor_sync(0xffffffffu, d1, 12);
            b1s = __shfl_xor_sync(0xffffffffu, d2, 4);
            b2s = __shfl_xor_sync(0xffffffffu, d2, 8);
            b3s = __shfl_xor_sync(0xffffffffu, d2, 12);
            d1 = (d1 + a1s) + (a2s + a3s);
            d2 = (d2 + b1s) + (b2s + b3s);
            a1s = __shfl_xor_sync(0xffffffffu, d1, 16);
            b1s = __shfl_xor_sync(0xffffffffu, d2, 16);
            d1 += a1s;
            d2 += b1s;
        }

        float a1 = E.x * d1;
        float a2 = E.y * fmaf(-E.z, d1, d2);

        h0 = fmaf(-a2, Cv.x, fmaf(-a1, A.x, z0 + Bv.x));
        h1 = fmaf(-a2, Cv.y, fmaf(-a1, A.y, z1 + Bv.y));
        h2 = fmaf(-a2, Cv.z, fmaf(-a1, A.z, y2 + Bv.z));
        h3 = fmaf(-a2, Cv.w, fmaf(-a1, A.w, y3 + Bv.w));

        *((float4*)(o + (size_t)t * 128) + lane) = make_float4(h0, h1, h2, h3);
    }
}

// ---------------- conv_h: raw fp32 h -> bf16 hi/lo triplets for GEMM2 ----------------
__global__ void conv_h()
{
    int idx = blockIdx.x * 256 + threadIdx.x;   // BT*32
    int bt = idx >> 5;
    int l = idx & 31;
    float4 hv = *((const float4*)g_Hraw + (size_t)bt * 32 + l);
    __nv_bfloat16 h[4], lo[4];
    split_bf16(hv.x, h[0], lo[0]); split_bf16(hv.y, h[1], lo[1]);
    split_bf16(hv.z, h[2], lo[2]); split_bf16(hv.w, h[3], lo[3]);
    unsigned w0 = pack2(h[0], lo[0]);
    unsigned w1 = pack2(h[0], h[1]);
    unsigned w2 = pack2(lo[1], h[1]);
    unsigned w3 = pack2(h[2], lo[2]);
    unsigned w4 = pack2(h[2], h[3]);
    unsigned w5 = pack2(lo[3], h[3]);
    uint2* op = (uint2*)(g_Hexp + (size_t)bt * K2EXP) + 3 * l;
    op[0] = make_uint2(w0, w1);
    op[1] = make_uint2(w2, w3);
    op[2] = make_uint2(w4, w5);
}

// ---------------- launch ----------------
extern "C" void kernel_launch(void* const* d_in, const int* in_sizes, int n_in,
                              void* d_out, int out_size)
{
    const float* u      = (const float*)d_in[0];
    const float* W_A    = (const float*)d_in[1];
    const float* b_A    = (const float*)d_in[2];
    const float* W_k    = (const float*)d_in[3];
    const float* b_k    = (const float*)d_in[4];
    const float* W_beta = (const float*)d_in[5];
    const float* b_beta = (const float*)d_in[6];
    const float* B_w    = (const float*)d_in[7];
    const float* B_b    = (const float*)d_in[8];
    const float* C      = (const float*)d_in[9];
    const float* D      = (const float*)d_in[10];
    float* out = (float*)d_out;

    pack_b1<<<(NP * DMODEL + 255) / 256, 256>>>(W_A, W_k, W_beta, B_w);
    pack_b2<<<(DMODEL * 128 + 255) / 256, 256>>>(C);
    conv_u<<<(BT * (DMODEL / 4)) / 256, 256>>>(u);

    // GEMM1: P[16384 x 512] = Uexp[16384 x 3072] * B1^T
    {
        __nv_bfloat16 *dA, *dB; float* dP;
        cudaGetSymbolAddress((void**)&dA, g_Uexp);
        cudaGetSymbolAddress((void**)&dB, g_B1);
        cudaGetSymbolAddress((void**)&dP, g_P);
        mma_gemm<K1EXP, K1EXP, K1EXP><<<dim3(NP / 128, BT / 128), 256>>>(
            dA, dB, dP, NP, nullptr, nullptr);
    }

    derive_kernel<<<BT, 128>>>(b_A, b_k, b_beta, B_b);

    scan_kernel<<<BATCH, 32>>>();
    conv_h<<<(BT * 32) / 256, 256>>>();

    // GEMM2: out[16384 x 1024] = Hexp[16384 x 384] * B2^T + u * D
    {
        __nv_bfloat16 *dA, *dB;
        cudaGetSymbolAddress((void**)&dA, g_Hexp);
        cudaGetSymbolAddress((void**)&dB, g_B2);
        mma_gemm<K2EXP, K2EXP, K2EXP><<<dim3(DMODEL / 128, BT / 128), 256>>>(
            dA, dB, out, DMODEL, u, D);
    }
}

// round 8
// speedup vs baseline: 1.2004x; 1.0580x over previous
#include <cuda_runtime.h>
#include <cuda_bf16.h>
#include <math.h>

#define BATCH   8
#define TT      2048
#define BT      16384      // BATCH*TT
#define DMODEL  1024
#define NP      512        // padded projection columns (450 real)
#define RECW    516        // floats per (b,t) record (float4 aligned)
#define K1EXP   3072       // 3 * 1024  (bf16 split blocks: [hi, lo, hi])
#define K2EXP   384        // 12 * 32   (interleaved per-lane triplets)

// ---------------- device scratch (no allocations allowed) ----------------
__device__ __align__(16) __nv_bfloat16 g_Uexp[(size_t)BT * K1EXP];      // A for GEMM1
__device__ __align__(16) __nv_bfloat16 g_B1[(size_t)NP * K1EXP];        // B for GEMM1
__device__ __align__(16) __nv_bfloat16 g_B2[(size_t)DMODEL * K2EXP];    // B for GEMM2
__device__ __align__(16) __nv_bfloat16 g_Hexp[(size_t)BT * K2EXP];      // A for GEMM2
__device__ float g_P[(size_t)BT * NP];                                  // raw projections fp32
__device__ __align__(16) float g_rec[(size_t)BT * RECW];                // derived scan records

// ---------------- helpers ----------------
__device__ __forceinline__ void split_bf16(float v, __nv_bfloat16& hi, __nv_bfloat16& lo)
{
    hi = __float2bfloat16(v);
    lo = __float2bfloat16(v - __bfloat162float(hi));
}

__device__ __forceinline__ unsigned pack2(__nv_bfloat16 a, __nv_bfloat16 b)
{
    __nv_bfloat162 p(a, b);
    return *(unsigned*)&p;
}

// ---------------- U -> bf16 hi/lo expansion: Uexp[bt][3K] = [hi | lo | hi] ----------------
__global__ void conv_u(const float* __restrict__ u)
{
    size_t i = (size_t)blockIdx.x * 256 + threadIdx.x;
    size_t row = i >> 8;
    int c = (int)(i & 255) * 4;
    float4 v = *(const float4*)(u + row * DMODEL + c);
    __nv_bfloat16 h[4], l[4];
    split_bf16(v.x, h[0], l[0]); split_bf16(v.y, h[1], l[1]);
    split_bf16(v.z, h[2], l[2]); split_bf16(v.w, h[3], l[3]);
    __nv_bfloat16* base = g_Uexp + row * K1EXP;
    *(uint2*)(base + c)        = *(uint2*)h;
    *(uint2*)(base + 1024 + c) = *(uint2*)l;
    *(uint2*)(base + 2048 + c) = *(uint2*)h;
}

// ---------------- pack B1[n][3K]: blocks [Bh | Bh | Bl] ----------------
__global__ void pack_b1(const float* __restrict__ W_A, const float* __restrict__ W_k,
                        const float* __restrict__ W_beta, const float* __restrict__ B_w)
{
    int idx = blockIdx.x * 256 + threadIdx.x;
    if (idx >= NP * DMODEL) return;
    int n = idx >> 10, k = idx & 1023;
    float v = 0.f;
    if (n < 64)        v = W_A[n * DMODEL + k];
    else if (n < 320)  v = W_k[(size_t)(n - 64) * DMODEL + k];
    else if (n < 322)  v = W_beta[(n - 320) * DMODEL + k];
    else if (n < 450)  v = B_w[(size_t)(n - 322) * DMODEL + k];
    __nv_bfloat16 hi, lo; split_bf16(v, hi, lo);
    __nv_bfloat16* base = g_B1 + (size_t)n * K1EXP;
    base[k] = hi; base[1024 + k] = hi; base[2048 + k] = lo;
}

// ---------------- pack B2[d][384]: k = 12*l + 3*i + s ; (Ch,Ch,Cl), n=l+32i ------
__global__ void pack_b2(const float* __restrict__ C)
{
    int idx = blockIdx.x * 256 + threadIdx.x;
    if (idx >= DMODEL * 128) return;
    int d = idx >> 7, n = idx & 127;
    int l = n & 31, i = n >> 5;
    float v = C[(size_t)d * 128 + n];
    __nv_bfloat16 hi, lo; split_bf16(v, hi, lo);
    __nv_bfloat16* base = g_B2 + (size_t)d * K2EXP + 12 * l + 3 * i;
    base[0] = hi; base[1] = hi; base[2] = lo;
}

// ---------------- bf16 HMMA GEMM: 128x128 CTA tile, 4 warps, 64x64 warp tile, BK=32 -------
// Doubles per-warp MAC:LDS ratio vs 32x64 tiles -> smem traffic ~375 cyc/iter vs
// tensor 256 cyc/iter (was 512 vs 256).
template <int KTOT, int LDA, int LDB>
__global__ __launch_bounds__(128)
void mma_gemm(const __nv_bfloat16* __restrict__ A, const __nv_bfloat16* __restrict__ B,
              float* __restrict__ Cout, int ldc,
              const float* __restrict__ uPtr, const float* __restrict__ Dvec)
{
    __shared__ unsigned sA[2][128 * 16];
    __shared__ unsigned sB[2][128 * 16];

    const int tid  = threadIdx.x;
    const int m0   = blockIdx.y * 128;
    const int n0   = blockIdx.x * 128;
    const int lrow = tid;                                 // staging: one full row per thread
    const int wid  = tid >> 5, lane = tid & 31;
    const int wm   = wid >> 1, wn = wid & 1;              // warp grid 2(M) x 2(N), tile 64x64
    const int grp  = lane >> 2, tig = lane & 3;

    const uint4* Ag = (const uint4*)A + (size_t)(m0 + lrow) * (LDA / 8);
    const uint4* Bg = (const uint4*)B + (size_t)(n0 + lrow) * (LDB / 8);

    const int sw    = (lrow & 7) << 1;
    const int sbase = lrow * 16;

    float acc[4][8][4];
#pragma unroll
    for (int im = 0; im < 4; im++)
#pragma unroll
        for (int in = 0; in < 8; in++)
#pragma unroll
            for (int q = 0; q < 4; q++) acc[im][in][q] = 0.f;

    constexpr int KIT = KTOT / 32;

    uint4 pa[4], pb[4];
#pragma unroll
    for (int q = 0; q < 4; q++) { pa[q] = Ag[q]; pb[q] = Bg[q]; }
    Ag += 4; Bg += 4;

    // store one full 32-col row (4 x uint4 = 16 words) with word-pair swizzle
#define STILE(dst, pv)                                                                   \
    do {                                                                                 \
        _Pragma("unroll")                                                                \
        for (int q = 0; q < 4; q++) {                                                    \
            ((uint2*)(dst))[(sbase + ((q * 4 + 0) ^ sw)) >> 1] =                         \
                make_uint2((pv)[q].x, (pv)[q].y);                                        \
            ((uint2*)(dst))[(sbase + ((q * 4 + 2) ^ sw)) >> 1] =                         \
                make_uint2((pv)[q].z, (pv)[q].w);                                        \
        }                                                                                \
    } while (0)

    STILE(sA[0], pa);
    STILE(sB[0], pb);
    __syncthreads();

    for (int it = 0; it < KIT; it++) {
        const int cur = it & 1, nxt = cur ^ 1;
        if (it + 1 < KIT) {
#pragma unroll
            for (int q = 0; q < 4; q++) { pa[q] = Ag[q]; pb[q] = Bg[q]; }
            Ag += 4; Bg += 4;
        }
        const unsigned* cA = sA[cur];
        const unsigned* cB = sB[cur];

#pragma unroll
        for (int kk = 0; kk < 2; kk++) {
            unsigned af[4][4], bf[8][2];
#pragma unroll
            for (int im = 0; im < 4; im++) {
                int r0 = wm * 64 + im * 16 + grp;
                int r1 = r0 + 8;
                int s0 = (r0 & 7) << 1;
                int s1 = (r1 & 7) << 1;
                af[im][0] = cA[r0 * 16 + ((kk * 8 + tig) ^ s0)];
                af[im][1] = cA[r1 * 16 + ((kk * 8 + tig) ^ s1)];
                af[im][2] = cA[r0 * 16 + ((kk * 8 + 4 + tig) ^ s0)];
                af[im][3] = cA[r1 * 16 + ((kk * 8 + 4 + tig) ^ s1)];
            }
#pragma unroll
            for (int in = 0; in < 8; in++) {
                int nr = wn * 64 + in * 8 + grp;
                int s  = (nr & 7) << 1;
                bf[in][0] = cB[nr * 16 + ((kk * 8 + tig) ^ s)];
                bf[in][1] = cB[nr * 16 + ((kk * 8 + 4 + tig) ^ s)];
            }
#pragma unroll
            for (int im = 0; im < 4; im++)
#pragma unroll
                for (int in = 0; in < 8; in++) {
                    float* c = acc[im][in];
                    asm volatile(
                        "mma.sync.aligned.m16n8k16.row.col.f32.bf16.bf16.f32 "
                        "{%0,%1,%2,%3}, {%4,%5,%6,%7}, {%8,%9}, {%0,%1,%2,%3};\n"
                        : "+f"(c[0]), "+f"(c[1]), "+f"(c[2]), "+f"(c[3])
                        : "r"(af[im][0]), "r"(af[im][1]), "r"(af[im][2]), "r"(af[im][3]),
                          "r"(bf[in][0]), "r"(bf[in][1]));
                }
        }

        if (it + 1 < KIT) {
            STILE(sA[nxt], pa);
            STILE(sB[nxt], pb);
            __syncthreads();
        }
    }
#undef STILE

#pragma unroll
    for (int im = 0; im < 4; im++) {
#pragma unroll
        for (int in = 0; in < 8; in++) {
            int row = m0 + wm * 64 + im * 16 + grp;
            int col = n0 + wn * 64 + in * 8 + tig * 2;
            float2 v01 = make_float2(acc[im][in][0], acc[im][in][1]);
            float2 v23 = make_float2(acc[im][in][2], acc[im][in][3]);
            if (uPtr) {
                size_t b0 = (size_t)row * ldc + col;
                size_t b1 = (size_t)(row + 8) * ldc + col;
                v01.x += uPtr[b0] * Dvec[col];
                v01.y += uPtr[b0 + 1] * Dvec[col + 1];
                v23.x += uPtr[b1] * Dvec[col];
                v23.y += uPtr[b1 + 1] * Dvec[col + 1];
            }
            *(float2*)(Cout + (size_t)row * ldc + col)       = v01;
            *(float2*)(Cout + (size_t)(row + 8) * ldc + col) = v23;
        }
    }
}

// ---------------- derive: projections -> per-step record (float4-lane layout) ----------
// record floats: [0,128) rot: lane l -> (S0,S1,D0,D1) at 4l ; [128,256) k1 (4l+i = n l+32i)
// [256,384) k2 ; [384,512) B ; [512] be1 [513] be2 [514] cc [515] pad
__global__ void derive_kernel(const float* __restrict__ bA, const float* __restrict__ bk,
                              const float* __restrict__ bbeta, const float* __restrict__ Bb)
{
    const int bt = blockIdx.x;
    const int n = threadIdx.x;               // 0..127
    const int l = n & 31, i = n >> 5;
    const float* p = g_P + (size_t)bt * NP;
    float* rc = g_rec + (size_t)bt * RECW;

    if (n < 64) {
        float a = fminf(fmaxf(p[n] + bA[n], 0.f), 100.f);
        float S = 1.f / (1.f + 0.01f * a);
        rc[4 * l + i]     = S;
        rc[4 * l + 2 + i] = 0.1f * a * S;    // DT*A*S
    }
    float k1 = p[64 + n]  + bk[n];
    float k2 = p[192 + n] + bk[128 + n];
    float Bv = p[322 + n] + Bb[n];

    float s1 = k1 * k1, s2 = k2 * k2, sx = k1 * k2;
#pragma unroll
    for (int off = 16; off; off >>= 1) {
        s1 += __shfl_xor_sync(0xffffffffu, s1, off);
        s2 += __shfl_xor_sync(0xffffffffu, s2, off);
        sx += __shfl_xor_sync(0xffffffffu, sx, off);
    }
    __shared__ float sm[12];
    __shared__ float bc[2];
    int w = n >> 5;
    if ((n & 31) == 0) { sm[w] = s1; sm[4 + w] = s2; sm[8 + w] = sx; }
    __syncthreads();
    if (n == 0) {
        float q1 = sm[0] + sm[1] + sm[2] + sm[3];
        float q2 = sm[4] + sm[5] + sm[6] + sm[7];
        float qx = sm[8] + sm[9] + sm[10] + sm[11];
        float i1 = 1.f / fmaxf(sqrtf(q1), 1e-12f);
        float i2 = 1.f / fmaxf(sqrtf(q2), 1e-12f);
        float be1 = 2.f / (1.f + expf(-(p[320] + bbeta[0])));
        float be2 = 2.f / (1.f + expf(-(p[321] + bbeta[1])));
        rc[512] = be1;
        rc[513] = be2;
        rc[514] = be1 * qx * i1 * i2;        // cc
        bc[0] = i1; bc[1] = i2;
    }
    __syncthreads();
    rc[128 + 4 * l + i] = k1 * bc[0];
    rc[256 + 4 * l + i] = k2 * bc[1];
    rc[384 + 4 * l + i] = Bv;
}

// ---------------- scan: EXACT R4 version (proven best): depth-4 prefetch, radix-2
// interleaved butterfly, in-loop bf16 hi/lo packing -> 3 x STG.64 ----------
__global__ __launch_bounds__(32)
void scan_kernel()
{
    const int b = blockIdx.x;
    const int lane = threadIdx.x;
    const float4* __restrict__ r4 = (const float4*)g_rec + (size_t)b * TT * (RECW / 4);
    __nv_bfloat16* __restrict__ o = g_Hexp + (size_t)b * TT * K2EXP;

    float h0 = 0.f, h1 = 0.f, h2 = 0.f, h3 = 0.f;

    float4 sv[4], av[4], cv[4], bv[4], ev[4];
#pragma unroll
    for (int p = 0; p < 4; p++) {
        const float4* rp = r4 + (size_t)p * (RECW / 4);
        sv[p] = rp[lane];
        av[p] = rp[32 + lane];
        cv[p] = rp[64 + lane];
        bv[p] = rp[96 + lane];
        ev[p] = rp[128];
    }

#pragma unroll 4
    for (int t = 0; t < TT; t++) {
        const int s = t & 3;
        const float4 S = sv[s], A = av[s], Cv = cv[s], Bv = bv[s], E = ev[s];

        const int tn = t + 4;
        if (tn < TT) {
            const float4* rp = r4 + (size_t)tn * (RECW / 4);
            sv[s] = rp[lane];
            av[s] = rp[32 + lane];
            cv[s] = rp[64 + lane];
            bv[s] = rp[96 + lane];
            ev[s] = rp[128];
        }

        // rotation: z_new = S*z - (DT*A*S)*y ; y_new = S*(DT*z + y)
        float z0 = fmaf(-S.z, h2, S.x * h0);
        float z1 = fmaf(-S.w, h3, S.y * h1);
        float y2 = S.x * fmaf(0.1f, h0, h2);
        float y3 = S.y * fmaf(0.1f, h1, h3);

        // two dots, one interleaved butterfly chain
        float d1 = fmaf(A.x, z0, A.y * z1); d1 = fmaf(A.z, y2, d1); d1 = fmaf(A.w, y3, d1);
        float d2 = fmaf(Cv.x, z0, Cv.y * z1); d2 = fmaf(Cv.z, y2, d2); d2 = fmaf(Cv.w, y3, d2);
#pragma unroll
        for (int off = 16; off; off >>= 1) {
            d1 += __shfl_xor_sync(0xffffffffu, d1, off);
            d2 += __shfl_xor_sync(0xffffffffu, d2, off);
        }

        float a1 = E.x * d1;
        float a2 = E.y * fmaf(-E.z, d1, d2);

        h0 = fmaf(-a2, Cv.x, fmaf(-a1, A.x, z0 + Bv.x));
        h1 = fmaf(-a2, Cv.y, fmaf(-a1, A.y, z1 + Bv.y));
        h2 = fmaf(-a2, Cv.z, fmaf(-a1, A.z, y2 + Bv.z));
        h3 = fmaf(-a2, Cv.w, fmaf(-a1, A.w, y3 + Bv.w));

        // pack 12 bf16 -> 3 x STG.64
        __nv_bfloat16 hh0, hl0, hh1, hl1, hh2, hl2, hh3, hl3;
        split_bf16(h0, hh0, hl0); split_bf16(h1, hh1, hl1);
        split_bf16(h2, hh2, hl2); split_bf16(h3, hh3, hl3);
        unsigned w0 = pack2(hh0, hl0);
        unsigned w1 = pack2(hh0, hh1);
        unsigned w2 = pack2(hl1, hh1);
        unsigned w3 = pack2(hh2, hl2);
        unsigned w4 = pack2(hh2, hh3);
        unsigned w5 = pack2(hl3, hh3);
        uint2* op = (uint2*)(o + (size_t)t * K2EXP) + 3 * lane;
        op[0] = make_uint2(w0, w1);
        op[1] = make_uint2(w2, w3);
        op[2] = make_uint2(w4, w5);
    }
}

// ---------------- launch ----------------
extern "C" void kernel_launch(void* const* d_in, const int* in_sizes, int n_in,
                              void* d_out, int out_size)
{
    const float* u      = (const float*)d_in[0];
    const float* W_A    = (const float*)d_in[1];
    const float* b_A    = (const float*)d_in[2];
    const float* W_k    = (const float*)d_in[3];
    const float* b_k    = (const float*)d_in[4];
    const float* W_beta = (const float*)d_in[5];
    const float* b_beta = (const float*)d_in[6];
    const float* B_w    = (const float*)d_in[7];
    const float* B_b    = (const float*)d_in[8];
    const float* C      = (const float*)d_in[9];
    const float* D      = (const float*)d_in[10];
    float* out = (float*)d_out;

    pack_b1<<<(NP * DMODEL + 255) / 256, 256>>>(W_A, W_k, W_beta, B_w);
    pack_b2<<<(DMODEL * 128 + 255) / 256, 256>>>(C);
    conv_u<<<(BT * (DMODEL / 4)) / 256, 256>>>(u);

    // GEMM1: P[16384 x 512] = Uexp[16384 x 3072] * B1^T
    {
        __nv_bfloat16 *dA, *dB; float* dP;
        cudaGetSymbolAddress((void**)&dA, g_Uexp);
        cudaGetSymbolAddress((void**)&dB, g_B1);
        cudaGetSymbolAddress((void**)&dP, g_P);
        mma_gemm<K1EXP, K1EXP, K1EXP><<<dim3(NP / 128, BT / 128), 128>>>(
            dA, dB, dP, NP, nullptr, nullptr);
    }

    derive_kernel<<<BT, 128>>>(b_A, b_k, b_beta, B_b);

    scan_kernel<<<BATCH, 32>>>();

    // GEMM2: out[16384 x 1024] = Hexp[16384 x 384] * B2^T + u * D
    {
        __nv_bfloat16 *dA, *dB;
        cudaGetSymbolAddress((void**)&dA, g_Hexp);
        cudaGetSymbolAddress((void**)&dB, g_B2);
        mma_gemm<K2EXP, K2EXP, K2EXP><<<dim3(DMODEL / 128, BT / 128), 128>>>(
            dA, dB, out, DMODEL, u, D);
    }
}

// round 11
// speedup vs baseline: 1.4427x; 1.2018x over previous
#include <cuda_runtime.h>
#include <cuda_bf16.h>
#include <cstdint>
#include <math.h>

#define BATCH   8
#define TT      2048
#define BT      16384      // BATCH*TT
#define DMODEL  1024
#define NP      512        // padded projection columns (450 real)
#define RECW    516        // floats per (b,t) record (float4 aligned)
#define K1EXP   3072       // 3 * 1024  (bf16 split blocks: [hi, lo, hi])
#define K2EXP   384        // 12 * 32   (interleaved per-lane triplets)

// ---------------- device scratch (no allocations allowed) ----------------
__device__ __align__(16) __nv_bfloat16 g_Uexp[(size_t)BT * K1EXP];      // A for GEMM1
__device__ __align__(16) __nv_bfloat16 g_B1[(size_t)NP * K1EXP];        // B for GEMM1
__device__ __align__(16) __nv_bfloat16 g_B2[(size_t)DMODEL * K2EXP];    // B for GEMM2
__device__ __align__(16) __nv_bfloat16 g_Hexp[(size_t)BT * K2EXP];      // A for GEMM2
__device__ float g_P[(size_t)BT * NP];                                  // raw projections fp32
__device__ __align__(16) float g_rec[(size_t)BT * RECW];                // derived scan records

// ---------------- helpers ----------------
__device__ __forceinline__ void split_bf16(float v, __nv_bfloat16& hi, __nv_bfloat16& lo)
{
    hi = __float2bfloat16(v);
    lo = __float2bfloat16(v - __bfloat162float(hi));
}

__device__ __forceinline__ unsigned pack2(__nv_bfloat16 a, __nv_bfloat16 b)
{
    __nv_bfloat162 p(a, b);
    return *(unsigned*)&p;
}

__device__ __forceinline__ uint32_t smem_u32(const void* p)
{
    uint32_t a;
    asm("{ .reg .u64 t; cvta.to.shared.u64 t, %1; cvt.u32.u64 %0, t; }" : "=r"(a) : "l"(p));
    return a;
}

#define LDSM4(r, a)                                                                     \
    asm volatile("ldmatrix.sync.aligned.m8n8.x4.shared.b16 {%0,%1,%2,%3}, [%4];"        \
                 : "=r"((r)[0]), "=r"((r)[1]), "=r"((r)[2]), "=r"((r)[3]) : "r"(a))

// ---------------- U -> bf16 hi/lo expansion: Uexp[bt][3K] = [hi | lo | hi] ----------------
__global__ void conv_u(const float* __restrict__ u)
{
    size_t i = (size_t)blockIdx.x * 256 + threadIdx.x;
    size_t row = i >> 8;
    int c = (int)(i & 255) * 4;
    float4 v = *(const float4*)(u + row * DMODEL + c);
    __nv_bfloat16 h[4], l[4];
    split_bf16(v.x, h[0], l[0]); split_bf16(v.y, h[1], l[1]);
    split_bf16(v.z, h[2], l[2]); split_bf16(v.w, h[3], l[3]);
    __nv_bfloat16* base = g_Uexp + row * K1EXP;
    *(uint2*)(base + c)        = *(uint2*)h;
    *(uint2*)(base + 1024 + c) = *(uint2*)l;
    *(uint2*)(base + 2048 + c) = *(uint2*)h;
}

// ---------------- pack B1[n][3K]: blocks [Bh | Bh | Bl] ----------------
__global__ void pack_b1(const float* __restrict__ W_A, const float* __restrict__ W_k,
                        const float* __restrict__ W_beta, const float* __restrict__ B_w)
{
    int idx = blockIdx.x * 256 + threadIdx.x;
    if (idx >= NP * DMODEL) return;
    int n = idx >> 10, k = idx & 1023;
    float v = 0.f;
    if (n < 64)        v = W_A[n * DMODEL + k];
    else if (n < 320)  v = W_k[(size_t)(n - 64) * DMODEL + k];
    else if (n < 322)  v = W_beta[(n - 320) * DMODEL + k];
    else if (n < 450)  v = B_w[(size_t)(n - 322) * DMODEL + k];
    __nv_bfloat16 hi, lo; split_bf16(v, hi, lo);
    __nv_bfloat16* base = g_B1 + (size_t)n * K1EXP;
    base[k] = hi; base[1024 + k] = hi; base[2048 + k] = lo;
}

// ---------------- pack B2[d][384]: k = 12*l + 3*i + s ; (Ch,Ch,Cl), n=l+32i ------
__global__ void pack_b2(const float* __restrict__ C)
{
    int idx = blockIdx.x * 256 + threadIdx.x;
    if (idx >= DMODEL * 128) return;
    int d = idx >> 7, n = idx & 127;
    int l = n & 31, i = n >> 5;
    float v = C[(size_t)d * 128 + n];
    __nv_bfloat16 hi, lo; split_bf16(v, hi, lo);
    __nv_bfloat16* base = g_B2 + (size_t)d * K2EXP + 12 * l + 3 * i;
    base[0] = hi; base[1] = hi; base[2] = lo;
}

// ---------------- bf16 HMMA GEMM: 128x128 tile, BK=32, 256 thr, 8 warps (4x2), ldmatrix ---
// SMEM tiles: 128 rows x 64B (4 x 16B chunks), chunk swizzle c ^= (row>>1)&3.
// Conflict-free for STS.128 staging AND 8-row ldmatrix column reads.
// Fragments via ldmatrix.m8n8.x4: A 2/kk, B 4/kk (two n-blocks per x4) -> 12 LDSM/iter
// vs 48 scalar LDS in the prior version.
template <int KTOT, int LDA, int LDB>
__global__ __launch_bounds__(256)
void mma_gemm(const __nv_bfloat16* __restrict__ A, const __nv_bfloat16* __restrict__ B,
              float* __restrict__ Cout, int ldc,
              const float* __restrict__ uPtr, const float* __restrict__ Dvec)
{
    __shared__ __align__(16) unsigned sA[2][128 * 16];
    __shared__ __align__(16) unsigned sB[2][128 * 16];

    const int tid  = threadIdx.x;
    const int m0   = blockIdx.y * 128;
    const int n0   = blockIdx.x * 128;
    const int lrow = tid >> 1, half = tid & 1;           // staging: row, k-half (32B each)
    const int wid  = tid >> 5, lane = tid & 31;
    const int wm   = wid >> 1, wn = wid & 1;             // warp 32(M) x 64(N)
    const int grp  = lane >> 2, tig = lane & 3;

    const uint4* Ag = (const uint4*)A + (size_t)(m0 + lrow) * (LDA / 8) + half * 2;
    const uint4* Bg = (const uint4*)B + (size_t)(n0 + lrow) * (LDB / 8) + half * 2;

    // staging byte offsets: 2 chunks (16B) per thread, chunk = half*2 + q
    uint32_t soff[2];
#pragma unroll
    for (int q = 0; q < 2; q++)
        soff[q] = (uint32_t)lrow * 64 + ((((uint32_t)(half * 2 + q)) ^ ((lrow >> 1) & 3)) << 4);

    // ldmatrix lane address components
    const uint32_t sA0 = smem_u32(&sA[0][0]);
    const uint32_t sB0 = smem_u32(&sB[0][0]);
    uint32_t aOff[2], aS[2];
#pragma unroll
    for (int im = 0; im < 2; im++) {
        int r = wm * 32 + im * 16 + (lane & 15);         // lanes 0-15 rows, 16-31 same rows
        aOff[im] = (uint32_t)r * 64;
        aS[im] = (r >> 1) & 3;
    }
    const uint32_t aC = (uint32_t)(lane >> 4);           // chunk select within k16
    uint32_t bOff[4], bS[4];
#pragma unroll
    for (int p = 0; p < 4; p++) {
        int r = wn * 64 + p * 16 + (lane & 7) + ((lane & 16) >> 1);
        bOff[p] = (uint32_t)r * 64;
        bS[p] = (r >> 1) & 3;
    }
    const uint32_t bC = (uint32_t)((lane >> 3) & 1);

    float acc[2][8][4];
#pragma unroll
    for (int im = 0; im < 2; im++)
#pragma unroll
        for (int in = 0; in < 8; in++)
#pragma unroll
            for (int q = 0; q < 4; q++) acc[im][in][q] = 0.f;

    constexpr int KIT = KTOT / 32;

    uint4 pa0 = Ag[0], pa1 = Ag[1], pb0 = Bg[0], pb1 = Bg[1];
    Ag += 4; Bg += 4;

#define STILE(dst, v0, v1)                                          \
    do {                                                            \
        *(uint4*)((char*)(dst) + soff[0]) = (v0);                   \
        *(uint4*)((char*)(dst) + soff[1]) = (v1);                   \
    } while (0)

    STILE(sA[0], pa0, pa1);
    STILE(sB[0], pb0, pb1);
    __syncthreads();

    for (int it = 0; it < KIT; it++) {
        const int cur = it & 1, nxt = cur ^ 1;
        if (it + 1 < KIT) {
            pa0 = Ag[0]; pa1 = Ag[1]; pb0 = Bg[0]; pb1 = Bg[1];
            Ag += 4; Bg += 4;
        }
        const uint32_t sAc = sA0 + (uint32_t)cur * 8192;
        const uint32_t sBc = sB0 + (uint32_t)cur * 8192;

#pragma unroll
        for (int kk = 0; kk < 2; kk++) {
            unsigned af[2][4], bf[8][2];
#pragma unroll
            for (int im = 0; im < 2; im++) {
                uint32_t ca = (uint32_t)(kk << 1) | aC;
                uint32_t addr = sAc + aOff[im] + ((ca ^ aS[im]) << 4);
                LDSM4(af[im], addr);
            }
#pragma unroll
            for (int p = 0; p < 4; p++) {
                uint32_t cb = (uint32_t)(kk << 1) | bC;
                uint32_t addr = sBc + bOff[p] + ((cb ^ bS[p]) << 4);
                unsigned t[4];
                LDSM4(t, addr);
                bf[2 * p][0] = t[0]; bf[2 * p][1] = t[1];
                bf[2 * p + 1][0] = t[2]; bf[2 * p + 1][1] = t[3];
            }
#pragma unroll
            for (int im = 0; im < 2; im++)
#pragma unroll
                for (int in = 0; in < 8; in++) {
                    float* c = acc[im][in];
                    asm volatile(
                        "mma.sync.aligned.m16n8k16.row.col.f32.bf16.bf16.f32 "
                        "{%0,%1,%2,%3}, {%4,%5,%6,%7}, {%8,%9}, {%0,%1,%2,%3};\n"
                        : "+f"(c[0]), "+f"(c[1]), "+f"(c[2]), "+f"(c[3])
                        : "r"(af[im][0]), "r"(af[im][1]), "r"(af[im][2]), "r"(af[im][3]),
                          "r"(bf[in][0]), "r"(bf[in][1]));
                }
        }

        if (it + 1 < KIT) {
            STILE(sA[nxt], pa0, pa1);
            STILE(sB[nxt], pb0, pb1);
            __syncthreads();
        }
    }
#undef STILE

    // epilogue (acc layout unchanged)
#pragma unroll
    for (int im = 0; im < 2; im++) {
#pragma unroll
        for (int in = 0; in < 8; in++) {
            int row = m0 + wm * 32 + im * 16 + grp;
            int col = n0 + wn * 64 + in * 8 + tig * 2;
            float2 v01 = make_float2(acc[im][in][0], acc[im][in][1]);
            float2 v23 = make_float2(acc[im][in][2], acc[im][in][3]);
            if (uPtr) {
                size_t b0 = (size_t)row * ldc + col;
                size_t b1 = (size_t)(row + 8) * ldc + col;
                v01.x += uPtr[b0] * Dvec[col];
                v01.y += uPtr[b0 + 1] * Dvec[col + 1];
                v23.x += uPtr[b1] * Dvec[col];
                v23.y += uPtr[b1 + 1] * Dvec[col + 1];
            }
            *(float2*)(Cout + (size_t)row * ldc + col)       = v01;
            *(float2*)(Cout + (size_t)(row + 8) * ldc + col) = v23;
        }
    }
}

// ---------------- derive: projections -> per-step record (float4-lane layout) ----------
// record floats: [0,128) rot: lane l -> (S0,S1,D0,D1) at 4l ; [128,256) k1 (4l+i = n l+32i)
// [256,384) k2 ; [384,512) B ; [512] be1 [513] be2 [514] cc [515] pad
__global__ void derive_kernel(const float* __restrict__ bA, const float* __restrict__ bk,
                              const float* __restrict__ bbeta, const float* __restrict__ Bb)
{
    const int bt = blockIdx.x;
    const int n = threadIdx.x;               // 0..127
    const int l = n & 31, i = n >> 5;
    const float* p = g_P + (size_t)bt * NP;
    float* rc = g_rec + (size_t)bt * RECW;

    if (n < 64) {
        float a = fminf(fmaxf(p[n] + bA[n], 0.f), 100.f);
        float S = 1.f / (1.f + 0.01f * a);
        rc[4 * l + i]     = S;
        rc[4 * l + 2 + i] = 0.1f * a * S;    // DT*A*S
    }
    float k1 = p[64 + n]  + bk[n];
    float k2 = p[192 + n] + bk[128 + n];
    float Bv = p[322 + n] + Bb[n];

    float s1 = k1 * k1, s2 = k2 * k2, sx = k1 * k2;
#pragma unroll
    for (int off = 16; off; off >>= 1) {
        s1 += __shfl_xor_sync(0xffffffffu, s1, off);
        s2 += __shfl_xor_sync(0xffffffffu, s2, off);
        sx += __shfl_xor_sync(0xffffffffu, sx, off);
    }
    __shared__ float sm[12];
    __shared__ float bc[2];
    int w = n >> 5;
    if ((n & 31) == 0) { sm[w] = s1; sm[4 + w] = s2; sm[8 + w] = sx; }
    __syncthreads();
    if (n == 0) {
        float q1 = sm[0] + sm[1] + sm[2] + sm[3];
        float q2 = sm[4] + sm[5] + sm[6] + sm[7];
        float qx = sm[8] + sm[9] + sm[10] + sm[11];
        float i1 = 1.f / fmaxf(sqrtf(q1), 1e-12f);
        float i2 = 1.f / fmaxf(sqrtf(q2), 1e-12f);
        float be1 = 2.f / (1.f + expf(-(p[320] + bbeta[0])));
        float be2 = 2.f / (1.f + expf(-(p[321] + bbeta[1])));
        rc[512] = be1;
        rc[513] = be2;
        rc[514] = be1 * qx * i1 * i2;        // cc
        bc[0] = i1; bc[1] = i2;
    }
    __syncthreads();
    rc[128 + 4 * l + i] = k1 * bc[0];
    rc[256 + 4 * l + i] = k2 * bc[1];
    rc[384 + 4 * l + i] = Bv;
}

// ---------------- scan: EXACT R4 (proven best): depth-4 prefetch, interleaved radix-2
// butterfly, in-loop bf16 hi/lo packing -> 3 x STG.64 ----------
__global__ __launch_bounds__(32)
void scan_kernel()
{
    const int b = blockIdx.x;
    const int lane = threadIdx.x;
    const float4* __restrict__ r4 = (const float4*)g_rec + (size_t)b * TT * (RECW / 4);
    __nv_bfloat16* __restrict__ o = g_Hexp + (size_t)b * TT * K2EXP;

    float h0 = 0.f, h1 = 0.f, h2 = 0.f, h3 = 0.f;

    float4 sv[4], av[4], cv[4], bv[4], ev[4];
#pragma unroll
    for (int p = 0; p < 4; p++) {
        const float4* rp = r4 + (size_t)p * (RECW / 4);
        sv[p] = rp[lane];
        av[p] = rp[32 + lane];
        cv[p] = rp[64 + lane];
        bv[p] = rp[96 + lane];
        ev[p] = rp[128];
    }

#pragma unroll 4
    for (int t = 0; t < TT; t++) {
        const int s = t & 3;
        const float4 S = sv[s], A = av[s], Cv = cv[s], Bv = bv[s], E = ev[s];

        const int tn = t + 4;
        if (tn < TT) {
            const float4* rp = r4 + (size_t)tn * (RECW / 4);
            sv[s] = rp[lane];
            av[s] = rp[32 + lane];
            cv[s] = rp[64 + lane];
            bv[s] = rp[96 + lane];
            ev[s] = rp[128];
        }

        float z0 = fmaf(-S.z, h2, S.x * h0);
        float z1 = fmaf(-S.w, h3, S.y * h1);
        float y2 = S.x * fmaf(0.1f, h0, h2);
        float y3 = S.y * fmaf(0.1f, h1, h3);

        float d1 = fmaf(A.x, z0, A.y * z1); d1 = fmaf(A.z, y2, d1); d1 = fmaf(A.w, y3, d1);
        float d2 = fmaf(Cv.x, z0, Cv.y * z1); d2 = fmaf(Cv.z, y2, d2); d2 = fmaf(Cv.w, y3, d2);
#pragma unroll
        for (int off = 16; off; off >>= 1) {
            d1 += __shfl_xor_sync(0xffffffffu, d1, off);
            d2 += __shfl_xor_sync(0xffffffffu, d2, off);
        }

        float a1 = E.x * d1;
        float a2 = E.y * fmaf(-E.z, d1, d2);

        h0 = fmaf(-a2, Cv.x, fmaf(-a1, A.x, z0 + Bv.x));
        h1 = fmaf(-a2, Cv.y, fmaf(-a1, A.y, z1 + Bv.y));
        h2 = fmaf(-a2, Cv.z, fmaf(-a1, A.z, y2 + Bv.z));
        h3 = fmaf(-a2, Cv.w, fmaf(-a1, A.w, y3 + Bv.w));

        __nv_bfloat16 hh0, hl0, hh1, hl1, hh2, hl2, hh3, hl3;
        split_bf16(h0, hh0, hl0); split_bf16(h1, hh1, hl1);
        split_bf16(h2, hh2, hl2); split_bf16(h3, hh3, hl3);
        unsigned w0 = pack2(hh0, hl0);
        unsigned w1 = pack2(hh0, hh1);
        unsigned w2 = pack2(hl1, hh1);
        unsigned w3 = pack2(hh2, hl2);
        unsigned w4 = pack2(hh2, hh3);
        unsigned w5 = pack2(hl3, hh3);
        uint2* op = (uint2*)(o + (size_t)t * K2EXP) + 3 * lane;
        op[0] = make_uint2(w0, w1);
        op[1] = make_uint2(w2, w3);
        op[2] = make_uint2(w4, w5);
    }
}

// ---------------- launch ----------------
extern "C" void kernel_launch(void* const* d_in, const int* in_sizes, int n_in,
                              void* d_out, int out_size)
{
    const float* u      = (const float*)d_in[0];
    const float* W_A    = (const float*)d_in[1];
    const float* b_A    = (const float*)d_in[2];
    const float* W_k    = (const float*)d_in[3];
    const float* b_k    = (const float*)d_in[4];
    const float* W_beta = (const float*)d_in[5];
    const float* b_beta = (const float*)d_in[6];
    const float* B_w    = (const float*)d_in[7];
    const float* B_b    = (const float*)d_in[8];
    const float* C      = (const float*)d_in[9];
    const float* D      = (const float*)d_in[10];
    float* out = (float*)d_out;

    pack_b1<<<(NP * DMODEL + 255) / 256, 256>>>(W_A, W_k, W_beta, B_w);
    pack_b2<<<(DMODEL * 128 + 255) / 256, 256>>>(C);
    conv_u<<<(BT * (DMODEL / 4)) / 256, 256>>>(u);

    // GEMM1: P[16384 x 512] = Uexp[16384 x 3072] * B1^T
    {
        __nv_bfloat16 *dA, *dB; float* dP;
        cudaGetSymbolAddress((void**)&dA, g_Uexp);
        cudaGetSymbolAddress((void**)&dB, g_B1);
        cudaGetSymbolAddress((void**)&dP, g_P);
        mma_gemm<K1EXP, K1EXP, K1EXP><<<dim3(NP / 128, BT / 128), 256>>>(
            dA, dB, dP, NP, nullptr, nullptr);
    }

    derive_kernel<<<BT, 128>>>(b_A, b_k, b_beta, B_b);

    scan_kernel<<<BATCH, 32>>>();

    // GEMM2: out[16384 x 1024] = Hexp[16384 x 384] * B2^T + u * D
    {
        __nv_bfloat16 *dA, *dB;
        cudaGetSymbolAddress((void**)&dA, g_Hexp);
        cudaGetSymbolAddress((void**)&dB, g_B2);
        mma_gemm<K2EXP, K2EXP, K2EXP><<<dim3(DMODEL / 128, BT / 128), 256>>>(
            dA, dB, out, DMODEL, u, D);
    }
}

// round 12
// speedup vs baseline: 1.6545x; 1.1468x over previous
#include <cuda_runtime.h>
#include <cuda_bf16.h>
#include <cstdint>
#include <math.h>

#define BATCH   8
#define TT      2048
#define BT      16384      // BATCH*TT
#define DMODEL  1024
#define NP      512        // padded projection columns (450 real)
#define RECW    516        // floats per (b,t) scan record (float4 aligned)
#define RECW2   388        // floats per (b,t) matrix-pass record (S,D,k1,k2,scalars)
#define K1EXP   3072       // 3 * 1024  (bf16 split blocks: [hi, lo, hi])
#define K2EXP   384        // 12 * 32   (interleaved per-lane triplets)
#define LCH     128        // chunk length
#define NCH     (BT / LCH) // 128 chunks (16 per batch)

// ---------------- device scratch (no allocations allowed) ----------------
__device__ __align__(16) __nv_bfloat16 g_Uexp[(size_t)BT * K1EXP];      // A for GEMM1
__device__ __align__(16) __nv_bfloat16 g_B1[(size_t)NP * K1EXP];        // B for GEMM1
__device__ __align__(16) __nv_bfloat16 g_B2[(size_t)DMODEL * K2EXP];    // B for GEMM2
__device__ __align__(16) __nv_bfloat16 g_Hexp[(size_t)BT * K2EXP];      // A for GEMM2
__device__ float g_P[(size_t)BT * NP];                                  // raw projections fp32
__device__ __align__(16) float g_rec[(size_t)BT * RECW];                // scan records (lane layout)
__device__ __align__(16) float g_rec2[(size_t)BT * RECW2];              // matrix-pass records (plain)
__device__ __align__(16) float g_Phi[(size_t)NCH * 128 * 128];          // chunk transition [ch][col][row]
__device__ __align__(16) float g_pend[NCH * 128];                       // chunk particular soln (P layout)
__device__ __align__(16) float g_hend[NCH * 128];                       // chunk end states (P layout)

// ---------------- helpers ----------------
__device__ __forceinline__ void split_bf16(float v, __nv_bfloat16& hi, __nv_bfloat16& lo)
{
    hi = __float2bfloat16(v);
    lo = __float2bfloat16(v - __bfloat162float(hi));
}

__device__ __forceinline__ unsigned pack2(__nv_bfloat16 a, __nv_bfloat16 b)
{
    __nv_bfloat162 p(a, b);
    return *(unsigned*)&p;
}

__device__ __forceinline__ uint32_t smem_u32(const void* p)
{
    uint32_t a;
    asm("{ .reg .u64 t; cvta.to.shared.u64 t, %1; cvt.u32.u64 %0, t; }" : "=r"(a) : "l"(p));
    return a;
}

#define LDSM4(r, a)                                                                     \
    asm volatile("ldmatrix.sync.aligned.m8n8.x4.shared.b16 {%0,%1,%2,%3}, [%4];"        \
                 : "=r"((r)[0]), "=r"((r)[1]), "=r"((r)[2]), "=r"((r)[3]) : "r"(a))

// ---------------- U -> bf16 hi/lo expansion: Uexp[bt][3K] = [hi | lo | hi] ----------------
__global__ void conv_u(const float* __restrict__ u)
{
    size_t i = (size_t)blockIdx.x * 256 + threadIdx.x;
    size_t row = i >> 8;
    int c = (int)(i & 255) * 4;
    float4 v = *(const float4*)(u + row * DMODEL + c);
    __nv_bfloat16 h[4], l[4];
    split_bf16(v.x, h[0], l[0]); split_bf16(v.y, h[1], l[1]);
    split_bf16(v.z, h[2], l[2]); split_bf16(v.w, h[3], l[3]);
    __nv_bfloat16* base = g_Uexp + row * K1EXP;
    *(uint2*)(base + c)        = *(uint2*)h;
    *(uint2*)(base + 1024 + c) = *(uint2*)l;
    *(uint2*)(base + 2048 + c) = *(uint2*)h;
}

// ---------------- pack B1[n][3K]: blocks [Bh | Bh | Bl] ----------------
__global__ void pack_b1(const float* __restrict__ W_A, const float* __restrict__ W_k,
                        const float* __restrict__ W_beta, const float* __restrict__ B_w)
{
    int idx = blockIdx.x * 256 + threadIdx.x;
    if (idx >= NP * DMODEL) return;
    int n = idx >> 10, k = idx & 1023;
    float v = 0.f;
    if (n < 64)        v = W_A[n * DMODEL + k];
    else if (n < 320)  v = W_k[(size_t)(n - 64) * DMODEL + k];
    else if (n < 322)  v = W_beta[(n - 320) * DMODEL + k];
    else if (n < 450)  v = B_w[(size_t)(n - 322) * DMODEL + k];
    __nv_bfloat16 hi, lo; split_bf16(v, hi, lo);
    __nv_bfloat16* base = g_B1 + (size_t)n * K1EXP;
    base[k] = hi; base[1024 + k] = hi; base[2048 + k] = lo;
}

// ---------------- pack B2[d][384]: k = 12*l + 3*i + s ; (Ch,Ch,Cl), n=l+32i ------
__global__ void pack_b2(const float* __restrict__ C)
{
    int idx = blockIdx.x * 256 + threadIdx.x;
    if (idx >= DMODEL * 128) return;
    int d = idx >> 7, n = idx & 127;
    int l = n & 31, i = n >> 5;
    float v = C[(size_t)d * 128 + n];
    __nv_bfloat16 hi, lo; split_bf16(v, hi, lo);
    __nv_bfloat16* base = g_B2 + (size_t)d * K2EXP + 12 * l + 3 * i;
    base[0] = hi; base[1] = hi; base[2] = lo;
}

// ---------------- bf16 HMMA GEMM (R11 ldmatrix version, proven) ----------
template <int KTOT, int LDA, int LDB>
__global__ __launch_bounds__(256)
void mma_gemm(const __nv_bfloat16* __restrict__ A, const __nv_bfloat16* __restrict__ B,
              float* __restrict__ Cout, int ldc,
              const float* __restrict__ uPtr, const float* __restrict__ Dvec)
{
    __shared__ __align__(16) unsigned sA[2][128 * 16];
    __shared__ __align__(16) unsigned sB[2][128 * 16];

    const int tid  = threadIdx.x;
    const int m0   = blockIdx.y * 128;
    const int n0   = blockIdx.x * 128;
    const int lrow = tid >> 1, half = tid & 1;
    const int wid  = tid >> 5, lane = tid & 31;
    const int wm   = wid >> 1, wn = wid & 1;
    const int grp  = lane >> 2, tig = lane & 3;

    const uint4* Ag = (const uint4*)A + (size_t)(m0 + lrow) * (LDA / 8) + half * 2;
    const uint4* Bg = (const uint4*)B + (size_t)(n0 + lrow) * (LDB / 8) + half * 2;

    uint32_t soff[2];
#pragma unroll
    for (int q = 0; q < 2; q++)
        soff[q] = (uint32_t)lrow * 64 + ((((uint32_t)(half * 2 + q)) ^ ((lrow >> 1) & 3)) << 4);

    const uint32_t sA0 = smem_u32(&sA[0][0]);
    const uint32_t sB0 = smem_u32(&sB[0][0]);
    uint32_t aOff[2], aS[2];
#pragma unroll
    for (int im = 0; im < 2; im++) {
        int r = wm * 32 + im * 16 + (lane & 15);
        aOff[im] = (uint32_t)r * 64;
        aS[im] = (r >> 1) & 3;
    }
    const uint32_t aC = (uint32_t)(lane >> 4);
    uint32_t bOff[4], bS[4];
#pragma unroll
    for (int p = 0; p < 4; p++) {
        int r = wn * 64 + p * 16 + (lane & 7) + ((lane & 16) >> 1);
        bOff[p] = (uint32_t)r * 64;
        bS[p] = (r >> 1) & 3;
    }
    const uint32_t bC = (uint32_t)((lane >> 3) & 1);

    float acc[2][8][4];
#pragma unroll
    for (int im = 0; im < 2; im++)
#pragma unroll
        for (int in = 0; in < 8; in++)
#pragma unroll
            for (int q = 0; q < 4; q++) acc[im][in][q] = 0.f;

    constexpr int KIT = KTOT / 32;

    uint4 pa0 = Ag[0], pa1 = Ag[1], pb0 = Bg[0], pb1 = Bg[1];
    Ag += 4; Bg += 4;

#define STILE(dst, v0, v1)                                          \
    do {                                                            \
        *(uint4*)((char*)(dst) + soff[0]) = (v0);                   \
        *(uint4*)((char*)(dst) + soff[1]) = (v1);                   \
    } while (0)

    STILE(sA[0], pa0, pa1);
    STILE(sB[0], pb0, pb1);
    __syncthreads();

    for (int it = 0; it < KIT; it++) {
        const int cur = it & 1, nxt = cur ^ 1;
        if (it + 1 < KIT) {
            pa0 = Ag[0]; pa1 = Ag[1]; pb0 = Bg[0]; pb1 = Bg[1];
            Ag += 4; Bg += 4;
        }
        const uint32_t sAc = sA0 + (uint32_t)cur * 8192;
        const uint32_t sBc = sB0 + (uint32_t)cur * 8192;

#pragma unroll
        for (int kk = 0; kk < 2; kk++) {
            unsigned af[2][4], bf[8][2];
#pragma unroll
            for (int im = 0; im < 2; im++) {
                uint32_t ca = (uint32_t)(kk << 1) | aC;
                uint32_t addr = sAc + aOff[im] + ((ca ^ aS[im]) << 4);
                LDSM4(af[im], addr);
            }
#pragma unroll
            for (int p = 0; p < 4; p++) {
                uint32_t cb = (uint32_t)(kk << 1) | bC;
                uint32_t addr = sBc + bOff[p] + ((cb ^ bS[p]) << 4);
                unsigned t[4];
                LDSM4(t, addr);
                bf[2 * p][0] = t[0]; bf[2 * p][1] = t[1];
                bf[2 * p + 1][0] = t[2]; bf[2 * p + 1][1] = t[3];
            }
#pragma unroll
            for (int im = 0; im < 2; im++)
#pragma unroll
                for (int in = 0; in < 8; in++) {
                    float* c = acc[im][in];
                    asm volatile(
                        "mma.sync.aligned.m16n8k16.row.col.f32.bf16.bf16.f32 "
                        "{%0,%1,%2,%3}, {%4,%5,%6,%7}, {%8,%9}, {%0,%1,%2,%3};\n"
                        : "+f"(c[0]), "+f"(c[1]), "+f"(c[2]), "+f"(c[3])
                        : "r"(af[im][0]), "r"(af[im][1]), "r"(af[im][2]), "r"(af[im][3]),
                          "r"(bf[in][0]), "r"(bf[in][1]));
                }
        }

        if (it + 1 < KIT) {
            STILE(sA[nxt], pa0, pa1);
            STILE(sB[nxt], pb0, pb1);
            __syncthreads();
        }
    }
#undef STILE

#pragma unroll
    for (int im = 0; im < 2; im++) {
#pragma unroll
        for (int in = 0; in < 8; in++) {
            int row = m0 + wm * 32 + im * 16 + grp;
            int col = n0 + wn * 64 + in * 8 + tig * 2;
            float2 v01 = make_float2(acc[im][in][0], acc[im][in][1]);
            float2 v23 = make_float2(acc[im][in][2], acc[im][in][3]);
            if (uPtr) {
                size_t b0 = (size_t)row * ldc + col;
                size_t b1 = (size_t)(row + 8) * ldc + col;
                v01.x += uPtr[b0] * Dvec[col];
                v01.y += uPtr[b0 + 1] * Dvec[col + 1];
                v23.x += uPtr[b1] * Dvec[col];
                v23.y += uPtr[b1 + 1] * Dvec[col + 1];
            }
            *(float2*)(Cout + (size_t)row * ldc + col)       = v01;
            *(float2*)(Cout + (size_t)(row + 8) * ldc + col) = v23;
        }
    }
}

// ---------------- derive: projections -> scan record (lane layout) + matrix record --------
// g_rec:  [0,128) rot (S0,S1,D0,D1)@4l ; [128,256) k1 ; [256,384) k2 ; [384,512) B ;
//         [512] be1 [513] be2 [514] cc [515] pad       (k indexed 4*(n&31)+(n>>5))
// g_rec2: [0,64) S_m ; [64,128) D_m ; [128,256) k1[n] ; [256,384) k2[n] ;
//         [384] be1 [385] be2 [386] cc [387] pad       (plain n/m indexing)
__global__ void derive_kernel(const float* __restrict__ bA, const float* __restrict__ bk,
                              const float* __restrict__ bbeta, const float* __restrict__ Bb)
{
    const int bt = blockIdx.x;
    const int n = threadIdx.x;               // 0..127
    const int l = n & 31, i = n >> 5;
    const float* p = g_P + (size_t)bt * NP;
    float* rc = g_rec + (size_t)bt * RECW;
    float* r2 = g_rec2 + (size_t)bt * RECW2;

    if (n < 64) {
        float a = fminf(fmaxf(p[n] + bA[n], 0.f), 100.f);
        float S = 1.f / (1.f + 0.01f * a);
        float Dv = 0.1f * a * S;
        rc[4 * l + i]     = S;
        rc[4 * l + 2 + i] = Dv;
        r2[n]      = S;
        r2[64 + n] = Dv;
    }
    float k1 = p[64 + n]  + bk[n];
    float k2 = p[192 + n] + bk[128 + n];
    float Bv = p[322 + n] + Bb[n];

    float s1 = k1 * k1, s2 = k2 * k2, sx = k1 * k2;
#pragma unroll
    for (int off = 16; off; off >>= 1) {
        s1 += __shfl_xor_sync(0xffffffffu, s1, off);
        s2 += __shfl_xor_sync(0xffffffffu, s2, off);
        sx += __shfl_xor_sync(0xffffffffu, sx, off);
    }
    __shared__ float sm[12];
    __shared__ float bc[2];
    int w = n >> 5;
    if ((n & 31) == 0) { sm[w] = s1; sm[4 + w] = s2; sm[8 + w] = sx; }
    __syncthreads();
    if (n == 0) {
        float q1 = sm[0] + sm[1] + sm[2] + sm[3];
        float q2 = sm[4] + sm[5] + sm[6] + sm[7];
        float qx = sm[8] + sm[9] + sm[10] + sm[11];
        float i1 = 1.f / fmaxf(sqrtf(q1), 1e-12f);
        float i2 = 1.f / fmaxf(sqrtf(q2), 1e-12f);
        float be1 = 2.f / (1.f + expf(-(p[320] + bbeta[0])));
        float be2 = 2.f / (1.f + expf(-(p[321] + bbeta[1])));
        float ccv = be1 * qx * i1 * i2;
        rc[512] = be1; rc[513] = be2; rc[514] = ccv;
        r2[384] = be1; r2[385] = be2; r2[386] = ccv;
        bc[0] = i1; bc[1] = i2;
    }
    __syncthreads();
    float k1n = k1 * bc[0];
    float k2n = k2 * bc[1];
    rc[128 + 4 * l + i] = k1n;
    rc[256 + 4 * l + i] = k2n;
    rc[384 + 4 * l + i] = Bv;
    r2[128 + n] = k1n;
    r2[256 + n] = k2n;
}

// ---------------- scan_chunk: R4 loop over one chunk. EMIT=0: p-pass (h0=0, store p_end).
// EMIT=1: output pass (h0 = chunk-start state, emit bf16 Hexp). One warp per chunk. ----
template <int EMIT>
__global__ __launch_bounds__(128)
void scan_chunk()
{
    const int wid = threadIdx.x >> 5;
    const int lane = threadIdx.x & 31;
    const int ch = blockIdx.x * 4 + wid;
    const float4* __restrict__ r4 = (const float4*)g_rec + (size_t)ch * LCH * (RECW / 4);
    __nv_bfloat16* __restrict__ o = g_Hexp + (size_t)ch * LCH * K2EXP;

    float h0 = 0.f, h1 = 0.f, h2 = 0.f, h3 = 0.f;
    if (EMIT && (ch & 15)) {
        float4 hv = *((const float4*)(g_hend + (size_t)(ch - 1) * 128) + lane);
        h0 = hv.x; h1 = hv.y; h2 = hv.z; h3 = hv.w;
    }

    float4 sv[4], av[4], cv[4], bv[4], ev[4];
#pragma unroll
    for (int p = 0; p < 4; p++) {
        const float4* rp = r4 + (size_t)p * (RECW / 4);
        sv[p] = rp[lane];
        av[p] = rp[32 + lane];
        cv[p] = rp[64 + lane];
        bv[p] = rp[96 + lane];
        ev[p] = rp[128];
    }

#pragma unroll 4
    for (int t = 0; t < LCH; t++) {
        const int s = t & 3;
        const float4 S = sv[s], A = av[s], Cv = cv[s], Bv = bv[s], E = ev[s];

        if (t + 4 < LCH) {
            const float4* rp = r4 + (size_t)(t + 4) * (RECW / 4);
            sv[s] = rp[lane];
            av[s] = rp[32 + lane];
            cv[s] = rp[64 + lane];
            bv[s] = rp[96 + lane];
            ev[s] = rp[128];
        }

        float z0 = fmaf(-S.z, h2, S.x * h0);
        float z1 = fmaf(-S.w, h3, S.y * h1);
        float y2 = S.x * fmaf(0.1f, h0, h2);
        float y3 = S.y * fmaf(0.1f, h1, h3);

        float d1 = fmaf(A.x, z0, A.y * z1); d1 = fmaf(A.z, y2, d1); d1 = fmaf(A.w, y3, d1);
        float d2 = fmaf(Cv.x, z0, Cv.y * z1); d2 = fmaf(Cv.z, y2, d2); d2 = fmaf(Cv.w, y3, d2);
#pragma unroll
        for (int off = 16; off; off >>= 1) {
            d1 += __shfl_xor_sync(0xffffffffu, d1, off);
            d2 += __shfl_xor_sync(0xffffffffu, d2, off);
        }

        float a1 = E.x * d1;
        float a2 = E.y * fmaf(-E.z, d1, d2);

        h0 = fmaf(-a2, Cv.x, fmaf(-a1, A.x, z0 + Bv.x));
        h1 = fmaf(-a2, Cv.y, fmaf(-a1, A.y, z1 + Bv.y));
        h2 = fmaf(-a2, Cv.z, fmaf(-a1, A.z, y2 + Bv.z));
        h3 = fmaf(-a2, Cv.w, fmaf(-a1, A.w, y3 + Bv.w));

        if (EMIT) {
            __nv_bfloat16 hh0, hl0, hh1, hl1, hh2, hl2, hh3, hl3;
            split_bf16(h0, hh0, hl0); split_bf16(h1, hh1, hl1);
            split_bf16(h2, hh2, hl2); split_bf16(h3, hh3, hl3);
            unsigned w0 = pack2(hh0, hl0);
            unsigned w1 = pack2(hh0, hh1);
            unsigned w2 = pack2(hl1, hh1);
            unsigned w3 = pack2(hh2, hl2);
            unsigned w4 = pack2(hh2, hh3);
            unsigned w5 = pack2(hl3, hh3);
            uint2* op = (uint2*)(o + (size_t)t * K2EXP) + 3 * lane;
            op[0] = make_uint2(w0, w1);
            op[1] = make_uint2(w2, w3);
            op[2] = make_uint2(w4, w5);
        }
    }

    if (!EMIT)
        *((float4*)(g_pend + (size_t)ch * 128) + lane) = make_float4(h0, h1, h2, h3);
}

// ---------------- chunk_mat: Phi_c = prod of M_t over chunk, applied to 128 basis columns.
// Grid (4 colgroups, NCH chunks) x 256 threads: col = cg*32 + tid>>3, q = tid&7 owns
// z rows m in [8q,8q+8) and y rows m+64 of its column (registers). Records staged in
// smem (plain layout g_rec2), double buffered. Dots combine over 8 q-lanes via shfl. ----
__global__ __launch_bounds__(256)
void chunk_mat()
{
    __shared__ float rec[2][RECW2];
    const int ch = blockIdx.y;
    const int tid = threadIdx.x;
    const int col = blockIdx.x * 32 + (tid >> 3);
    const int q = tid & 7;

    const float* rbase = g_rec2 + (size_t)ch * LCH * RECW2;

    float zc[8], yc[8];
#pragma unroll
    for (int i = 0; i < 8; i++) {
        int m = 8 * q + i;
        zc[i] = (m == col) ? 1.f : 0.f;
        yc[i] = (m + 64 == col) ? 1.f : 0.f;
    }

    rec[0][tid] = rbase[tid];
    if (tid + 256 < RECW2) rec[0][tid + 256] = rbase[tid + 256];
    __syncthreads();

    for (int t = 0; t < LCH; t++) {
        const int cur = t & 1;
        const float* rc = rec[cur];

        float pf0 = 0.f, pf1 = 0.f;
        if (t + 1 < LCH) {
            const float* rn = rbase + (size_t)(t + 1) * RECW2;
            pf0 = rn[tid];
            if (tid + 256 < RECW2) pf1 = rn[tid + 256];
        }

        const float be1 = rc[384], be2 = rc[385], cc = rc[386];

        float d1 = 0.f, d2 = 0.f;
        float k1z[8], k1y[8], k2z[8], k2y[8];
#pragma unroll
        for (int i = 0; i < 8; i++) {
            const int m = 8 * q + i;
            float S  = rc[m];
            float Dv = rc[64 + m];
            k1z[i] = rc[128 + m]; k1y[i] = rc[192 + m];
            k2z[i] = rc[256 + m]; k2y[i] = rc[320 + m];
            float zn = fmaf(-Dv, yc[i], S * zc[i]);
            float yn = S * fmaf(0.1f, zc[i], yc[i]);
            d1 = fmaf(k1z[i], zn, fmaf(k1y[i], yn, d1));
            d2 = fmaf(k2z[i], zn, fmaf(k2y[i], yn, d2));
            zc[i] = zn; yc[i] = yn;
        }
#pragma unroll
        for (int off = 1; off < 8; off <<= 1) {
            d1 += __shfl_xor_sync(0xffffffffu, d1, off);
            d2 += __shfl_xor_sync(0xffffffffu, d2, off);
        }
        const float a1 = be1 * d1;
        const float a2 = be2 * fmaf(-cc, d1, d2);
#pragma unroll
        for (int i = 0; i < 8; i++) {
            zc[i] = fmaf(-a2, k2z[i], fmaf(-a1, k1z[i], zc[i]));
            yc[i] = fmaf(-a2, k2y[i], fmaf(-a1, k1y[i], yc[i]));
        }

        if (t + 1 < LCH) {
            __syncthreads();
            const int nxt = cur ^ 1;
            rec[nxt][tid] = pf0;
            if (tid + 256 < RECW2) rec[nxt][tid + 256] = pf1;
            __syncthreads();
        }
    }

    float* ph = g_Phi + ((size_t)ch * 128 + col) * 128;
#pragma unroll
    for (int i = 0; i < 8; i++) {
        ph[8 * q + i]      = zc[i];
        ph[64 + 8 * q + i] = yc[i];
    }
}

// ---------------- combine: per batch, sequential over 16 chunks: h = Phi_c h + p_c.
// One warp per batch (8 blocks). h kept in P layout: lane holds n = lane+32j. ----
__global__ __launch_bounds__(32)
void combine()
{
    const int b = blockIdx.x;
    const int lane = threadIdx.x;
    float a0 = 0.f, a1v = 0.f, a2v = 0.f, a3v = 0.f;

    for (int c = 0; c < 16; c++) {
        const int ch = b * 16 + c;
        const float* Phi = g_Phi + (size_t)ch * 128 * 128;
        float b0 = 0.f, b1 = 0.f, b2 = 0.f, b3 = 0.f;
#pragma unroll
        for (int i = 0; i < 4; i++) {
            float hsrc = (i == 0) ? a0 : (i == 1) ? a1v : (i == 2) ? a2v : a3v;
            for (int cl = 0; cl < 32; cl++) {
                float hc = __shfl_sync(0xffffffffu, hsrc, cl);
                const float* pc = Phi + (size_t)(32 * i + cl) * 128;
                b0 = fmaf(hc, pc[lane], b0);
                b1 = fmaf(hc, pc[32 + lane], b1);
                b2 = fmaf(hc, pc[64 + lane], b2);
                b3 = fmaf(hc, pc[96 + lane], b3);
            }
        }
        const float4 pe = *((const float4*)(g_pend + (size_t)ch * 128) + lane);
        a0 = b0 + pe.x; a1v = b1 + pe.y; a2v = b2 + pe.z; a3v = b3 + pe.w;
        *((float4*)(g_hend + (size_t)ch * 128) + lane) = make_float4(a0, a1v, a2v, a3v);
    }
}

// ---------------- launch ----------------
extern "C" void kernel_launch(void* const* d_in, const int* in_sizes, int n_in,
                              void* d_out, int out_size)
{
    const float* u      = (const float*)d_in[0];
    const float* W_A    = (const float*)d_in[1];
    const float* b_A    = (const float*)d_in[2];
    const float* W_k    = (const float*)d_in[3];
    const float* b_k    = (const float*)d_in[4];
    const float* W_beta = (const float*)d_in[5];
    const float* b_beta = (const float*)d_in[6];
    const float* B_w    = (const float*)d_in[7];
    const float* B_b    = (const float*)d_in[8];
    const float* C      = (const float*)d_in[9];
    const float* D      = (const float*)d_in[10];
    float* out = (float*)d_out;

    pack_b1<<<(NP * DMODEL + 255) / 256, 256>>>(W_A, W_k, W_beta, B_w);
    pack_b2<<<(DMODEL * 128 + 255) / 256, 256>>>(C);
    conv_u<<<(BT * (DMODEL / 4)) / 256, 256>>>(u);

    // GEMM1: P[16384 x 512] = Uexp[16384 x 3072] * B1^T
    {
        __nv_bfloat16 *dA, *dB; float* dP;
        cudaGetSymbolAddress((void**)&dA, g_Uexp);
        cudaGetSymbolAddress((void**)&dB, g_B1);
        cudaGetSymbolAddress((void**)&dP, g_P);
        mma_gemm<K1EXP, K1EXP, K1EXP><<<dim3(NP / 128, BT / 128), 256>>>(
            dA, dB, dP, NP, nullptr, nullptr);
    }

    derive_kernel<<<BT, 128>>>(b_A, b_k, b_beta, B_b);

    // chunked parallel scan
    scan_chunk<0><<<NCH / 4, 128>>>();               // per-chunk particular solutions
    chunk_mat<<<dim3(4, NCH), 256>>>();              // per-chunk transition matrices
    combine<<<BATCH, 32>>>();                        // sequential chunk-level recurrence
    scan_chunk<1><<<NCH / 4, 128>>>();               // emit full outputs

    // GEMM2: out[16384 x 1024] = Hexp[16384 x 384] * B2^T + u * D
    {
        __nv_bfloat16 *dA, *dB;
        cudaGetSymbolAddress((void**)&dA, g_Hexp);
        cudaGetSymbolAddress((void**)&dB, g_B2);
        mma_gemm<K2EXP, K2EXP, K2EXP><<<dim3(DMODEL / 128, BT / 128), 256>>>(
            dA, dB, out, DMODEL, u, D);
    }
}

// round 13
// speedup vs baseline: 1.6868x; 1.0195x over previous
#include <cuda_runtime.h>
#include <cuda_bf16.h>
#include <cstdint>
#include <math.h>

#define BATCH   8
#define TT      2048
#define BT      16384      // BATCH*TT
#define DMODEL  1024
#define NP      512        // padded projection columns (450 real)
#define RECW    516        // floats per (b,t) scan record (float4 aligned)
#define RECW2   388        // floats per (b,t) matrix-pass record (S,D,k1,k2,scalars)
#define K1EXP   3072       // 3 * 1024  (bf16 split blocks: [hi, lo, hi])
#define K2EXP   384        // 12 * 32   (interleaved per-lane triplets)
#define LCH     128        // chunk length
#define NCH     (BT / LCH) // 128 chunks (16 per batch)

// ---------------- device scratch (no allocations allowed) ----------------
__device__ __align__(16) __nv_bfloat16 g_Uexp[(size_t)BT * K1EXP];      // A for GEMM1
__device__ __align__(16) __nv_bfloat16 g_B1[(size_t)NP * K1EXP];        // B for GEMM1
__device__ __align__(16) __nv_bfloat16 g_B2[(size_t)DMODEL * K2EXP];    // B for GEMM2
__device__ __align__(16) __nv_bfloat16 g_Hexp[(size_t)BT * K2EXP];      // A for GEMM2
__device__ float g_P[(size_t)BT * NP];                                  // raw projections fp32
__device__ __align__(16) float g_rec[(size_t)BT * RECW];                // scan records (lane layout)
__device__ __align__(16) float g_rec2[(size_t)BT * RECW2];              // matrix-pass records (plain)
__device__ __align__(16) float g_Phi[(size_t)NCH * 128 * 128];          // chunk transition [ch][col][row]
__device__ __align__(16) float g_pend[NCH * 128];                       // chunk particular soln (P layout)
__device__ __align__(16) float g_hend[NCH * 128];                       // chunk end states (P layout)

// ---------------- helpers ----------------
__device__ __forceinline__ void split_bf16(float v, __nv_bfloat16& hi, __nv_bfloat16& lo)
{
    hi = __float2bfloat16(v);
    lo = __float2bfloat16(v - __bfloat162float(hi));
}

__device__ __forceinline__ unsigned pack2(__nv_bfloat16 a, __nv_bfloat16 b)
{
    __nv_bfloat162 p(a, b);
    return *(unsigned*)&p;
}

__device__ __forceinline__ uint32_t smem_u32(const void* p)
{
    uint32_t a;
    asm("{ .reg .u64 t; cvta.to.shared.u64 t, %1; cvt.u32.u64 %0, t; }" : "=r"(a) : "l"(p));
    return a;
}

#define LDSM4(r, a)                                                                     \
    asm volatile("ldmatrix.sync.aligned.m8n8.x4.shared.b16 {%0,%1,%2,%3}, [%4];"        \
                 : "=r"((r)[0]), "=r"((r)[1]), "=r"((r)[2]), "=r"((r)[3]) : "r"(a))

// ---------------- U -> bf16 hi/lo expansion: Uexp[bt][3K] = [hi | lo | hi] ----------------
__global__ void conv_u(const float* __restrict__ u)
{
    size_t i = (size_t)blockIdx.x * 256 + threadIdx.x;
    size_t row = i >> 8;
    int c = (int)(i & 255) * 4;
    float4 v = *(const float4*)(u + row * DMODEL + c);
    __nv_bfloat16 h[4], l[4];
    split_bf16(v.x, h[0], l[0]); split_bf16(v.y, h[1], l[1]);
    split_bf16(v.z, h[2], l[2]); split_bf16(v.w, h[3], l[3]);
    __nv_bfloat16* base = g_Uexp + row * K1EXP;
    *(uint2*)(base + c)        = *(uint2*)h;
    *(uint2*)(base + 1024 + c) = *(uint2*)l;
    *(uint2*)(base + 2048 + c) = *(uint2*)h;
}

// ---------------- pack B1[n][3K]: blocks [Bh | Bh | Bl] ----------------
__global__ void pack_b1(const float* __restrict__ W_A, const float* __restrict__ W_k,
                        const float* __restrict__ W_beta, const float* __restrict__ B_w)
{
    int idx = blockIdx.x * 256 + threadIdx.x;
    if (idx >= NP * DMODEL) return;
    int n = idx >> 10, k = idx & 1023;
    float v = 0.f;
    if (n < 64)        v = W_A[n * DMODEL + k];
    else if (n < 320)  v = W_k[(size_t)(n - 64) * DMODEL + k];
    else if (n < 322)  v = W_beta[(n - 320) * DMODEL + k];
    else if (n < 450)  v = B_w[(size_t)(n - 322) * DMODEL + k];
    __nv_bfloat16 hi, lo; split_bf16(v, hi, lo);
    __nv_bfloat16* base = g_B1 + (size_t)n * K1EXP;
    base[k] = hi; base[1024 + k] = hi; base[2048 + k] = lo;
}

// ---------------- pack B2[d][384]: k = 12*l + 3*i + s ; (Ch,Ch,Cl), n=l+32i ------
__global__ void pack_b2(const float* __restrict__ C)
{
    int idx = blockIdx.x * 256 + threadIdx.x;
    if (idx >= DMODEL * 128) return;
    int d = idx >> 7, n = idx & 127;
    int l = n & 31, i = n >> 5;
    float v = C[(size_t)d * 128 + n];
    __nv_bfloat16 hi, lo; split_bf16(v, hi, lo);
    __nv_bfloat16* base = g_B2 + (size_t)d * K2EXP + 12 * l + 3 * i;
    base[0] = hi; base[1] = hi; base[2] = lo;
}

// ---------------- bf16 HMMA GEMM (R11 ldmatrix version, proven) ----------
template <int KTOT, int LDA, int LDB>
__global__ __launch_bounds__(256)
void mma_gemm(const __nv_bfloat16* __restrict__ A, const __nv_bfloat16* __restrict__ B,
              float* __restrict__ Cout, int ldc,
              const float* __restrict__ uPtr, const float* __restrict__ Dvec)
{
    __shared__ __align__(16) unsigned sA[2][128 * 16];
    __shared__ __align__(16) unsigned sB[2][128 * 16];

    const int tid  = threadIdx.x;
    const int m0   = blockIdx.y * 128;
    const int n0   = blockIdx.x * 128;
    const int lrow = tid >> 1, half = tid & 1;
    const int wid  = tid >> 5, lane = tid & 31;
    const int wm   = wid >> 1, wn = wid & 1;
    const int grp  = lane >> 2, tig = lane & 3;

    const uint4* Ag = (const uint4*)A + (size_t)(m0 + lrow) * (LDA / 8) + half * 2;
    const uint4* Bg = (const uint4*)B + (size_t)(n0 + lrow) * (LDB / 8) + half * 2;

    uint32_t soff[2];
#pragma unroll
    for (int q = 0; q < 2; q++)
        soff[q] = (uint32_t)lrow * 64 + ((((uint32_t)(half * 2 + q)) ^ ((lrow >> 1) & 3)) << 4);

    const uint32_t sA0 = smem_u32(&sA[0][0]);
    const uint32_t sB0 = smem_u32(&sB[0][0]);
    uint32_t aOff[2], aS[2];
#pragma unroll
    for (int im = 0; im < 2; im++) {
        int r = wm * 32 + im * 16 + (lane & 15);
        aOff[im] = (uint32_t)r * 64;
        aS[im] = (r >> 1) & 3;
    }
    const uint32_t aC = (uint32_t)(lane >> 4);
    uint32_t bOff[4], bS[4];
#pragma unroll
    for (int p = 0; p < 4; p++) {
        int r = wn * 64 + p * 16 + (lane & 7) + ((lane & 16) >> 1);
        bOff[p] = (uint32_t)r * 64;
        bS[p] = (r >> 1) & 3;
    }
    const uint32_t bC = (uint32_t)((lane >> 3) & 1);

    float acc[2][8][4];
#pragma unroll
    for (int im = 0; im < 2; im++)
#pragma unroll
        for (int in = 0; in < 8; in++)
#pragma unroll
            for (int q = 0; q < 4; q++) acc[im][in][q] = 0.f;

    constexpr int KIT = KTOT / 32;

    uint4 pa0 = Ag[0], pa1 = Ag[1], pb0 = Bg[0], pb1 = Bg[1];
    Ag += 4; Bg += 4;

#define STILE(dst, v0, v1)                                          \
    do {                                                            \
        *(uint4*)((char*)(dst) + soff[0]) = (v0);                   \
        *(uint4*)((char*)(dst) + soff[1]) = (v1);                   \
    } while (0)

    STILE(sA[0], pa0, pa1);
    STILE(sB[0], pb0, pb1);
    __syncthreads();

    for (int it = 0; it < KIT; it++) {
        const int cur = it & 1, nxt = cur ^ 1;
        if (it + 1 < KIT) {
            pa0 = Ag[0]; pa1 = Ag[1]; pb0 = Bg[0]; pb1 = Bg[1];
            Ag += 4; Bg += 4;
        }
        const uint32_t sAc = sA0 + (uint32_t)cur * 8192;
        const uint32_t sBc = sB0 + (uint32_t)cur * 8192;

#pragma unroll
        for (int kk = 0; kk < 2; kk++) {
            unsigned af[2][4], bf[8][2];
#pragma unroll
            for (int im = 0; im < 2; im++) {
                uint32_t ca = (uint32_t)(kk << 1) | aC;
                uint32_t addr = sAc + aOff[im] + ((ca ^ aS[im]) << 4);
                LDSM4(af[im], addr);
            }
#pragma unroll
            for (int p = 0; p < 4; p++) {
                uint32_t cb = (uint32_t)(kk << 1) | bC;
                uint32_t addr = sBc + bOff[p] + ((cb ^ bS[p]) << 4);
                unsigned t[4];
                LDSM4(t, addr);
                bf[2 * p][0] = t[0]; bf[2 * p][1] = t[1];
                bf[2 * p + 1][0] = t[2]; bf[2 * p + 1][1] = t[3];
            }
#pragma unroll
            for (int im = 0; im < 2; im++)
#pragma unroll
                for (int in = 0; in < 8; in++) {
                    float* c = acc[im][in];
                    asm volatile(
                        "mma.sync.aligned.m16n8k16.row.col.f32.bf16.bf16.f32 "
                        "{%0,%1,%2,%3}, {%4,%5,%6,%7}, {%8,%9}, {%0,%1,%2,%3};\n"
                        : "+f"(c[0]), "+f"(c[1]), "+f"(c[2]), "+f"(c[3])
                        : "r"(af[im][0]), "r"(af[im][1]), "r"(af[im][2]), "r"(af[im][3]),
                          "r"(bf[in][0]), "r"(bf[in][1]));
                }
        }

        if (it + 1 < KIT) {
            STILE(sA[nxt], pa0, pa1);
            STILE(sB[nxt], pb0, pb1);
            __syncthreads();
        }
    }
#undef STILE

#pragma unroll
    for (int im = 0; im < 2; im++) {
#pragma unroll
        for (int in = 0; in < 8; in++) {
            int row = m0 + wm * 32 + im * 16 + grp;
            int col = n0 + wn * 64 + in * 8 + tig * 2;
            float2 v01 = make_float2(acc[im][in][0], acc[im][in][1]);
            float2 v23 = make_float2(acc[im][in][2], acc[im][in][3]);
            if (uPtr) {
                size_t b0 = (size_t)row * ldc + col;
                size_t b1 = (size_t)(row + 8) * ldc + col;
                v01.x += uPtr[b0] * Dvec[col];
                v01.y += uPtr[b0 + 1] * Dvec[col + 1];
                v23.x += uPtr[b1] * Dvec[col];
                v23.y += uPtr[b1 + 1] * Dvec[col + 1];
            }
            *(float2*)(Cout + (size_t)row * ldc + col)       = v01;
            *(float2*)(Cout + (size_t)(row + 8) * ldc + col) = v23;
        }
    }
}

// ---------------- derive: projections -> scan record (lane layout) + matrix record --------
__global__ void derive_kernel(const float* __restrict__ bA, const float* __restrict__ bk,
                              const float* __restrict__ bbeta, const float* __restrict__ Bb)
{
    const int bt = blockIdx.x;
    const int n = threadIdx.x;               // 0..127
    const int l = n & 31, i = n >> 5;
    const float* p = g_P + (size_t)bt * NP;
    float* rc = g_rec + (size_t)bt * RECW;
    float* r2 = g_rec2 + (size_t)bt * RECW2;

    if (n < 64) {
        float a = fminf(fmaxf(p[n] + bA[n], 0.f), 100.f);
        float S = 1.f / (1.f + 0.01f * a);
        float Dv = 0.1f * a * S;
        rc[4 * l + i]     = S;
        rc[4 * l + 2 + i] = Dv;
        r2[n]      = S;
        r2[64 + n] = Dv;
    }
    float k1 = p[64 + n]  + bk[n];
    float k2 = p[192 + n] + bk[128 + n];
    float Bv = p[322 + n] + Bb[n];

    float s1 = k1 * k1, s2 = k2 * k2, sx = k1 * k2;
#pragma unroll
    for (int off = 16; off; off >>= 1) {
        s1 += __shfl_xor_sync(0xffffffffu, s1, off);
        s2 += __shfl_xor_sync(0xffffffffu, s2, off);
        sx += __shfl_xor_sync(0xffffffffu, sx, off);
    }
    __shared__ float sm[12];
    __shared__ float bc[2];
    int w = n >> 5;
    if ((n & 31) == 0) { sm[w] = s1; sm[4 + w] = s2; sm[8 + w] = sx; }
    __syncthreads();
    if (n == 0) {
        float q1 = sm[0] + sm[1] + sm[2] + sm[3];
        float q2 = sm[4] + sm[5] + sm[6] + sm[7];
        float qx = sm[8] + sm[9] + sm[10] + sm[11];
        float i1 = 1.f / fmaxf(sqrtf(q1), 1e-12f);
        float i2 = 1.f / fmaxf(sqrtf(q2), 1e-12f);
        float be1 = 2.f / (1.f + expf(-(p[320] + bbeta[0])));
        float be2 = 2.f / (1.f + expf(-(p[321] + bbeta[1])));
        float ccv = be1 * qx * i1 * i2;
        rc[512] = be1; rc[513] = be2; rc[514] = ccv;
        r2[384] = be1; r2[385] = be2; r2[386] = ccv;
        bc[0] = i1; bc[1] = i2;
    }
    __syncthreads();
    float k1n = k1 * bc[0];
    float k2n = k2 * bc[1];
    rc[128 + 4 * l + i] = k1n;
    rc[256 + 4 * l + i] = k2n;
    rc[384 + 4 * l + i] = Bv;
    r2[128 + n] = k1n;
    r2[256 + n] = k2n;
}

// ---------------- scan_chunk: R4 loop over one chunk. EMIT=0: p-pass (h0=0, store p_end).
// EMIT=1: output pass (h0 = chunk-start state, emit bf16 Hexp). One warp per chunk. ----
template <int EMIT>
__global__ __launch_bounds__(128)
void scan_chunk()
{
    const int wid = threadIdx.x >> 5;
    const int lane = threadIdx.x & 31;
    const int ch = blockIdx.x * 4 + wid;
    const float4* __restrict__ r4 = (const float4*)g_rec + (size_t)ch * LCH * (RECW / 4);
    __nv_bfloat16* __restrict__ o = g_Hexp + (size_t)ch * LCH * K2EXP;

    float h0 = 0.f, h1 = 0.f, h2 = 0.f, h3 = 0.f;
    if (EMIT && (ch & 15)) {
        float4 hv = *((const float4*)(g_hend + (size_t)(ch - 1) * 128) + lane);
        h0 = hv.x; h1 = hv.y; h2 = hv.z; h3 = hv.w;
    }

    float4 sv[4], av[4], cv[4], bv[4], ev[4];
#pragma unroll
    for (int p = 0; p < 4; p++) {
        const float4* rp = r4 + (size_t)p * (RECW / 4);
        sv[p] = rp[lane];
        av[p] = rp[32 + lane];
        cv[p] = rp[64 + lane];
        bv[p] = rp[96 + lane];
        ev[p] = rp[128];
    }

#pragma unroll 4
    for (int t = 0; t < LCH; t++) {
        const int s = t & 3;
        const float4 S = sv[s], A = av[s], Cv = cv[s], Bv = bv[s], E = ev[s];

        if (t + 4 < LCH) {
            const float4* rp = r4 + (size_t)(t + 4) * (RECW / 4);
            sv[s] = rp[lane];
            av[s] = rp[32 + lane];
            cv[s] = rp[64 + lane];
            bv[s] = rp[96 + lane];
            ev[s] = rp[128];
        }

        float z0 = fmaf(-S.z, h2, S.x * h0);
        float z1 = fmaf(-S.w, h3, S.y * h1);
        float y2 = S.x * fmaf(0.1f, h0, h2);
        float y3 = S.y * fmaf(0.1f, h1, h3);

        float d1 = fmaf(A.x, z0, A.y * z1); d1 = fmaf(A.z, y2, d1); d1 = fmaf(A.w, y3, d1);
        float d2 = fmaf(Cv.x, z0, Cv.y * z1); d2 = fmaf(Cv.z, y2, d2); d2 = fmaf(Cv.w, y3, d2);
#pragma unroll
        for (int off = 16; off; off >>= 1) {
            d1 += __shfl_xor_sync(0xffffffffu, d1, off);
            d2 += __shfl_xor_sync(0xffffffffu, d2, off);
        }

        float a1 = E.x * d1;
        float a2 = E.y * fmaf(-E.z, d1, d2);

        h0 = fmaf(-a2, Cv.x, fmaf(-a1, A.x, z0 + Bv.x));
        h1 = fmaf(-a2, Cv.y, fmaf(-a1, A.y, z1 + Bv.y));
        h2 = fmaf(-a2, Cv.z, fmaf(-a1, A.z, y2 + Bv.z));
        h3 = fmaf(-a2, Cv.w, fmaf(-a1, A.w, y3 + Bv.w));

        if (EMIT) {
            __nv_bfloat16 hh0, hl0, hh1, hl1, hh2, hl2, hh3, hl3;
            split_bf16(h0, hh0, hl0); split_bf16(h1, hh1, hl1);
            split_bf16(h2, hh2, hl2); split_bf16(h3, hh3, hl3);
            unsigned w0 = pack2(hh0, hl0);
            unsigned w1 = pack2(hh0, hh1);
            unsigned w2 = pack2(hl1, hh1);
            unsigned w3 = pack2(hh2, hl2);
            unsigned w4 = pack2(hh2, hh3);
            unsigned w5 = pack2(hl3, hh3);
            uint2* op = (uint2*)(o + (size_t)t * K2EXP) + 3 * lane;
            op[0] = make_uint2(w0, w1);
            op[1] = make_uint2(w2, w3);
            op[2] = make_uint2(w4, w5);
        }
    }

    if (!EMIT)
        *((float4*)(g_pend + (size_t)ch * 128) + lane) = make_float4(h0, h1, h2, h3);
}

// ---------------- chunk_mat: Phi_c = prod of M_t over chunk, on 128 basis columns. --------
// v2: float4 LDS (12 LDS.128/step vs 48 LDS.32), 4-step staged records (0.5 syncs/step
// vs 2). col = blockIdx.x*32 + tid>>3; q = tid&7 owns z rows [8q,8q+8) and y rows +64. ----
__global__ __launch_bounds__(256)
void chunk_mat()
{
    __shared__ __align__(16) float rec[2][4 * RECW2];
    const int ch = blockIdx.y;
    const int tid = threadIdx.x;
    const int col = blockIdx.x * 32 + (tid >> 3);
    const int q = tid & 7;

    const float* rbase = g_rec2 + (size_t)ch * LCH * RECW2;
    constexpr int BLKF = 4 * RECW2;          // 1552 floats per 4-step block

    float zc[8], yc[8];
#pragma unroll
    for (int i = 0; i < 8; i++) {
        int m = 8 * q + i;
        zc[i] = (m == col) ? 1.f : 0.f;
        yc[i] = (m + 64 == col) ? 1.f : 0.f;
    }

    for (int j = tid; j < BLKF; j += 256) rec[0][j] = rbase[j];
    __syncthreads();

    for (int blk = 0; blk < LCH / 4; blk++) {
        const int cur = blk & 1;
        const bool more = (blk + 1 < LCH / 4);
        float pf[7];
        if (more) {
            const float* rn = rbase + (size_t)(blk + 1) * BLKF;
#pragma unroll
            for (int j = 0; j < 7; j++) {
                int idx = tid + 256 * j;
                pf[j] = (idx < BLKF) ? rn[idx] : 0.f;
            }
        }

#pragma unroll
        for (int ts = 0; ts < 4; ts++) {
            const float* rc = &rec[cur][ts * RECW2];
            const float be1 = rc[384], be2 = rc[385], cc = rc[386];

            float Sm[8], Dm[8], K1z[8], K1y[8], K2z[8], K2y[8];
            *(float4*)&Sm[0]  = *(const float4*)(rc + 8 * q);
            *(float4*)&Sm[4]  = *(const float4*)(rc + 8 * q + 4);
            *(float4*)&Dm[0]  = *(const float4*)(rc + 64 + 8 * q);
            *(float4*)&Dm[4]  = *(const float4*)(rc + 64 + 8 * q + 4);
            *(float4*)&K1z[0] = *(const float4*)(rc + 128 + 8 * q);
            *(float4*)&K1z[4] = *(const float4*)(rc + 128 + 8 * q + 4);
            *(float4*)&K1y[0] = *(const float4*)(rc + 192 + 8 * q);
            *(float4*)&K1y[4] = *(const float4*)(rc + 192 + 8 * q + 4);
            *(float4*)&K2z[0] = *(const float4*)(rc + 256 + 8 * q);
            *(float4*)&K2z[4] = *(const float4*)(rc + 256 + 8 * q + 4);
            *(float4*)&K2y[0] = *(const float4*)(rc + 320 + 8 * q);
            *(float4*)&K2y[4] = *(const float4*)(rc + 320 + 8 * q + 4);

            float d1 = 0.f, d2 = 0.f;
#pragma unroll
            for (int i = 0; i < 8; i++) {
                float zn = fmaf(-Dm[i], yc[i], Sm[i] * zc[i]);
                float yn = Sm[i] * fmaf(0.1f, zc[i], yc[i]);
                d1 = fmaf(K1z[i], zn, fmaf(K1y[i], yn, d1));
                d2 = fmaf(K2z[i], zn, fmaf(K2y[i], yn, d2));
                zc[i] = zn; yc[i] = yn;
            }
#pragma unroll
            for (int off = 1; off < 8; off <<= 1) {
                d1 += __shfl_xor_sync(0xffffffffu, d1, off);
                d2 += __shfl_xor_sync(0xffffffffu, d2, off);
            }
            const float a1 = be1 * d1;
            const float a2 = be2 * fmaf(-cc, d1, d2);
#pragma unroll
            for (int i = 0; i < 8; i++) {
                zc[i] = fmaf(-a2, K2z[i], fmaf(-a1, K1z[i], zc[i]));
                yc[i] = fmaf(-a2, K2y[i], fmaf(-a1, K1y[i], yc[i]));
            }
        }

        if (more) {
            __syncthreads();
            float* dst = rec[cur ^ 1];
#pragma unroll
            for (int j = 0; j < 7; j++) {
                int idx = tid + 256 * j;
                if (idx < BLKF) dst[idx] = pf[j];
            }
            __syncthreads();
        }
    }

    float* ph = g_Phi + ((size_t)ch * 128 + col) * 128;
#pragma unroll
    for (int i = 0; i < 8; i++) {
        ph[8 * q + i]      = zc[i];
        ph[64 + 8 * q + i] = yc[i];
    }
}

// ---------------- combine: per batch, sequential over 16 chunks: h = Phi_c h + p_c. ----
__global__ __launch_bounds__(32)
void combine()
{
    const int b = blockIdx.x;
    const int lane = threadIdx.x;
    float a0 = 0.f, a1v = 0.f, a2v = 0.f, a3v = 0.f;

    for (int c = 0; c < 16; c++) {
        const int ch = b * 16 + c;
        const float* Phi = g_Phi + (size_t)ch * 128 * 128;
        float b0 = 0.f, b1 = 0.f, b2 = 0.f, b3 = 0.f;
#pragma unroll
        for (int i = 0; i < 4; i++) {
            float hsrc = (i == 0) ? a0 : (i == 1) ? a1v : (i == 2) ? a2v : a3v;
            for (int cl = 0; cl < 32; cl++) {
                float hc = __shfl_sync(0xffffffffu, hsrc, cl);
                const float* pc = Phi + (size_t)(32 * i + cl) * 128;
                b0 = fmaf(hc, pc[lane], b0);
                b1 = fmaf(hc, pc[32 + lane], b1);
                b2 = fmaf(hc, pc[64 + lane], b2);
                b3 = fmaf(hc, pc[96 + lane], b3);
            }
        }
        const float4 pe = *((const float4*)(g_pend + (size_t)ch * 128) + lane);
        a0 = b0 + pe.x; a1v = b1 + pe.y; a2v = b2 + pe.z; a3v = b3 + pe.w;
        *((float4*)(g_hend + (size_t)ch * 128) + lane) = make_float4(a0, a1v, a2v, a3v);
    }
}

// ---------------- launch ----------------
extern "C" void kernel_launch(void* const* d_in, const int* in_sizes, int n_in,
                              void* d_out, int out_size)
{
    const float* u      = (const float*)d_in[0];
    const float* W_A    = (const float*)d_in[1];
    const float* b_A    = (const float*)d_in[2];
    const float* W_k    = (const float*)d_in[3];
    const float* b_k    = (const float*)d_in[4];
    const float* W_beta = (const float*)d_in[5];
    const float* b_beta = (const float*)d_in[6];
    const float* B_w    = (const float*)d_in[7];
    const float* B_b    = (const float*)d_in[8];
    const float* C      = (const float*)d_in[9];
    const float* D      = (const float*)d_in[10];
    float* out = (float*)d_out;

    pack_b1<<<(NP * DMODEL + 255) / 256, 256>>>(W_A, W_k, W_beta, B_w);
    pack_b2<<<(DMODEL * 128 + 255) / 256, 256>>>(C);
    conv_u<<<(BT * (DMODEL / 4)) / 256, 256>>>(u);

    // GEMM1: P[16384 x 512] = Uexp[16384 x 3072] * B1^T
    {
        __nv_bfloat16 *dA, *dB; float* dP;
        cudaGetSymbolAddress((void**)&dA, g_Uexp);
        cudaGetSymbolAddress((void**)&dB, g_B1);
        cudaGetSymbolAddress((void**)&dP, g_P);
        mma_gemm<K1EXP, K1EXP, K1EXP><<<dim3(NP / 128, BT / 128), 256>>>(
            dA, dB, dP, NP, nullptr, nullptr);
    }

    derive_kernel<<<BT, 128>>>(b_A, b_k, b_beta, B_b);

    // chunked parallel scan
    scan_chunk<0><<<NCH / 4, 128>>>();               // per-chunk particular solutions
    chunk_mat<<<dim3(4, NCH), 256>>>();              // per-chunk transition matrices
    combine<<<BATCH, 32>>>();                        // sequential chunk-level recurrence
    scan_chunk<1><<<NCH / 4, 128>>>();               // emit full outputs

    // GEMM2: out[16384 x 1024] = Hexp[16384 x 384] * B2^T + u * D
    {
        __nv_bfloat16 *dA, *dB;
        cudaGetSymbolAddress((void**)&dA, g_Hexp);
        cudaGetSymbolAddress((void**)&dB, g_B2);
        mma_gemm<K2EXP, K2EXP, K2EXP><<<dim3(DMODEL / 128, BT / 128), 256>>>(
            dA, dB, out, DMODEL, u, D);
    }
}